// round 6
// baseline (speedup 1.0000x reference)
#include <cuda_runtime.h>
#include <math.h>
#include <stdint.h>

// Problem constants
#define B_   32
#define SEQ_ 577
#define H_   16
#define HD_  88
#define D_   1408
#define IDX_ 24
#define M_   (B_ * SEQ_)   // 18464

typedef unsigned long long ull;

// Scratch (device globals)
__device__ float g_Q[(size_t)M_ * D_];
__device__ float g_K[(size_t)M_ * D_];
__device__ float g_V[(size_t)M_ * D_];
__device__ float g_C[(size_t)M_ * D_];
__device__ float g_cos[SEQ_ * 44];
__device__ float g_sin[SEQ_ * 44];

// ---------------------------------------------------------------------------
// f32x2 packed helpers (native Blackwell FFMA2 on the fma pipe)
// ---------------------------------------------------------------------------
__device__ __forceinline__ void fma2(ull& d, ull a, ull b) {
    asm("fma.rn.f32x2 %0, %1, %2, %0;" : "+l"(d) : "l"(a), "l"(b));
}
__device__ __forceinline__ void mul2(ull& d, ull a, ull b) {
    asm("mul.rn.f32x2 %0, %1, %2;" : "=l"(d) : "l"(a), "l"(b));
}
__device__ __forceinline__ ull pack2(float lo, float hi) {
    ull r;
    asm("mov.b64 %0, {%1, %2};" : "=l"(r) : "r"(__float_as_uint(lo)), "r"(__float_as_uint(hi)));
    return r;
}
__device__ __forceinline__ void unpack2(ull v, float& lo, float& hi) {
    uint32_t l, h;
    asm("mov.b64 {%0, %1}, %2;" : "=r"(l), "=r"(h) : "l"(v));
    lo = __uint_as_float(l); hi = __uint_as_float(h);
}

// ---------------------------------------------------------------------------
// GEMM: C[M][1408] = A[M][1408] @ W[1408][1408]^T + bias   (fp32, FFMA2)
// 128x128x16 tiles, 256 threads, 8x8 microtile as 8x4 f32x2 accumulators.
// A staged into smem PRE-DUPLICATED ((a,a) pairs) so the packed outer product
// needs no per-k register packing. Double-buffered.
// ---------------------------------------------------------------------------
constexpr int BM = 128, BN = 128, BK = 16;
constexpr int NKT = D_ / BK;          // 88
constexpr int ASTR = 260;             // floats per Asd row (16B-aligned, low conflict)
constexpr int BSTR = 132;             // floats per Bs row
constexpr int ABUF = BK * ASTR;       // 4160 floats
constexpr int BBUF = BK * BSTR;       // 2112 floats
constexpr int GSMEM = (2 * ABUF + 2 * BBUF) * 4;   // 50176 bytes

__global__ __launch_bounds__(256) void gemm_f32x2_kernel(
    const float* __restrict__ A, const float* __restrict__ W,
    const float* __restrict__ bias, float* __restrict__ C, int M)
{
    extern __shared__ __align__(16) float sm[];
    float* Asd = sm;                      // [2][BK][ASTR]
    float* Bs  = sm + 2 * ABUF;           // [2][BK][BSTR]

    const int t  = threadIdx.x;
    const int tm = t >> 4;                // 0..15 -> rows 8tm..8tm+7
    const int tn = t & 15;                // 0..15 -> cols 8tn..8tn+7
    const int bm = blockIdx.y * BM;
    const int bn = blockIdx.x * BN;

    ull acc[8][4];
#pragma unroll
    for (int i = 0; i < 8; i++)
#pragma unroll
        for (int j = 0; j < 4; j++) acc[i][j] = 0ull;

    float4 ra[2], rb[2];

    auto ldg = [&](int kt) {
        const int k0 = kt * BK;
#pragma unroll
        for (int i = 0; i < 2; i++) {
            int q = t + 256 * i;          // 0..511
            int r = q >> 2;               // 0..127
            int c = q & 3;                // k-quad
            int gm = bm + r; if (gm >= M) gm = M - 1;   // clamp (rows >= M unused)
            ra[i] = *(const float4*)&A[(size_t)gm * D_ + k0 + c * 4];
            rb[i] = *(const float4*)&W[(size_t)(bn + r) * D_ + k0 + c * 4];
        }
    };
    auto sts = [&](int buf) {
        float* Ab = Asd + buf * ABUF;
        float* Bb = Bs  + buf * BBUF;
#pragma unroll
        for (int i = 0; i < 2; i++) {
            int q = t + 256 * i;
            int r = q >> 2;
            int c = q & 3;
            float av[4] = {ra[i].x, ra[i].y, ra[i].z, ra[i].w};
            float bv[4] = {rb[i].x, rb[i].y, rb[i].z, rb[i].w};
#pragma unroll
            for (int j = 0; j < 4; j++) {
                *(float2*)&Ab[(c * 4 + j) * ASTR + 2 * r] = make_float2(av[j], av[j]);
                Bb[(c * 4 + j) * BSTR + r] = bv[j];
            }
        }
    };

    ldg(0); sts(0); __syncthreads();

    for (int kt = 0; kt < NKT; kt++) {
        const int buf = kt & 1;
        if (kt + 1 < NKT) ldg(kt + 1);

        const float* Ab = Asd + buf * ABUF + (tm << 4);
        const float* Bb = Bs  + buf * BBUF + (tn << 3);
#pragma unroll
        for (int k = 0; k < BK; k++) {
            const ulonglong2* pa = (const ulonglong2*)(Ab + k * ASTR);
            const ulonglong2* pb = (const ulonglong2*)(Bb + k * BSTR);
            ulonglong2 a01 = pa[0], a23 = pa[1], a45 = pa[2], a67 = pa[3];
            ulonglong2 b01 = pb[0], b23 = pb[1];
            ull a2[8] = {a01.x, a01.y, a23.x, a23.y, a45.x, a45.y, a67.x, a67.y};
            ull b2[4] = {b01.x, b01.y, b23.x, b23.y};
#pragma unroll
            for (int i = 0; i < 8; i++)
#pragma unroll
                for (int j = 0; j < 4; j++)
                    fma2(acc[i][j], a2[i], b2[j]);
        }

        if (kt + 1 < NKT) { sts(buf ^ 1); __syncthreads(); }
    }

    // epilogue
    float4 bs0 = *(const float4*)&bias[bn + tn * 8];
    float4 bs1 = *(const float4*)&bias[bn + tn * 8 + 4];
#pragma unroll
    for (int i = 0; i < 8; i++) {
        int gm = bm + tm * 8 + i;
        if (gm >= M) continue;
        float c0, c1, c2, c3, c4, c5, c6, c7;
        unpack2(acc[i][0], c0, c1);
        unpack2(acc[i][1], c2, c3);
        unpack2(acc[i][2], c4, c5);
        unpack2(acc[i][3], c6, c7);
        float4 v0 = make_float4(c0 + bs0.x, c1 + bs0.y, c2 + bs0.z, c3 + bs0.w);
        float4 v1 = make_float4(c4 + bs1.x, c5 + bs1.y, c6 + bs1.z, c7 + bs1.w);
        *(float4*)&C[(size_t)gm * D_ + bn + tn * 8]     = v0;
        *(float4*)&C[(size_t)gm * D_ + bn + tn * 8 + 4] = v1;
    }
}

// ---------------------------------------------------------------------------
// Rope tables + apply
// ---------------------------------------------------------------------------
__global__ void rope_init_kernel()
{
    int idx = blockIdx.x * blockDim.x + threadIdx.x;
    if (idx >= SEQ_ * 44) return;
    int s = idx / 44, j = idx % 44;
    double f = 0.0;
    if (s != SEQ_ - 1) {
        int fx = s % IDX_, fy = s / IDX_;
        int i = (j < 22) ? j : j - 22;
        double rf = exp((-2.0 * (double)i / 44.0) * log(10000.0));
        double coord = (j < 22) ? (double)(fx + 1) : (double)(fy + 1);
        f = coord * rf;
    }
    g_cos[idx] = (float)cos(f);
    g_sin[idx] = (float)sin(f);
}

__global__ void rope_apply_kernel()
{
    int idx = blockIdx.x * blockDim.x + threadIdx.x;
    const int total = B_ * SEQ_ * H_ * 44;
    if (idx >= total) return;
    int j    = idx % 44;
    int rest = idx / 44;
    int s    = (rest / H_) % SEQ_;
    size_t base = (size_t)rest * HD_ + 2 * j;
    float c  = g_cos[s * 44 + j];
    float sn = g_sin[s * 44 + j];

    float a = g_Q[base], b = g_Q[base + 1];
    g_Q[base]     = a * c - b * sn;
    g_Q[base + 1] = a * sn + b * c;
    a = g_K[base]; b = g_K[base + 1];
    g_K[base]     = a * c - b * sn;
    g_K[base + 1] = a * sn + b * c;
}

// ---------------------------------------------------------------------------
// Flash attention (fp32, f32x2 inner loops). Block = (b, h, 32 queries).
// ---------------------------------------------------------------------------
__global__ __launch_bounds__(256) void attn_kernel(
    const float* __restrict__ Q, const float* __restrict__ K,
    const float* __restrict__ V, float* __restrict__ O)
{
    const int qt = blockIdx.x, h = blockIdx.y, b = blockIdx.z;
    const int q0 = qt * 32;

    __shared__ __align__(16) float Qs[32][92];
    __shared__ __align__(16) float Ks[32][92];
    __shared__ __align__(16) float VsT[HD_][36];
    __shared__ __align__(16) float Ps[32][36];
    __shared__ float m_sh[32], l_sh[32], corr_sh[32];

    const int t    = threadIdx.x;
    const int lane = t & 31;
    const int warp = t >> 5;
    const int dbase = warp * 11;
    const int srow = t >> 3;
    const int ssub = t & 7;

    for (int idx = t; idx < 32 * HD_; idx += 256) {
        int qq = idx / HD_, d = idx % HD_;
        int s = q0 + qq;
        Qs[qq][d] = (s < SEQ_) ? Q[(((size_t)b * SEQ_ + s) * H_ + h) * HD_ + d] : 0.f;
    }
    if (t < 32) { m_sh[t] = -1e30f; l_sh[t] = 0.f; }
    __syncthreads();

    ull qr2[44];
#pragma unroll
    for (int d4 = 0; d4 < 22; d4++) {
        ulonglong2 qq4 = *(const ulonglong2*)&Qs[lane][d4 * 4];
        qr2[2 * d4]     = qq4.x;
        qr2[2 * d4 + 1] = qq4.y;
    }

    ull acc2[11];
#pragma unroll
    for (int i = 0; i < 11; i++) acc2[i] = 0ull;

    const float scale = 0.10660035817780521f;   // 88^-0.5

    for (int k0 = 0; k0 < SEQ_; k0 += 32) {
        for (int idx = t; idx < 32 * HD_; idx += 256) {
            int kk = idx / HD_, d = idx % HD_;
            int s = k0 + kk;
            float kv = 0.f, vv = 0.f;
            if (s < SEQ_) {
                size_t gg = (((size_t)b * SEQ_ + s) * H_ + h) * HD_ + d;
                kv = K[gg]; vv = V[gg];
            }
            Ks[kk][d]  = kv;
            VsT[d][kk] = vv;
        }
        __syncthreads();

        // scores: q = lane, kk = warp*4 + j   (f32x2 dot products)
        {
            const int q = lane;
#pragma unroll
            for (int j = 0; j < 4; j++) {
                int kk = warp * 4 + j;
                ull s2 = 0ull;
                const float* krow = &Ks[kk][0];
#pragma unroll
                for (int d4 = 0; d4 < 22; d4++) {
                    ulonglong2 kv = *(const ulonglong2*)(krow + d4 * 4);
                    fma2(s2, qr2[2 * d4],     kv.x);
                    fma2(s2, qr2[2 * d4 + 1], kv.y);
                }
                float slo, shi; unpack2(s2, slo, shi);
                float s = slo + shi;
                Ps[q][kk] = (k0 + kk < SEQ_) ? s * scale : -1e30f;
            }
        }
        __syncthreads();

        // online softmax: 8 threads per row
        {
            float m_old = m_sh[srow];
            float4 pv = *(const float4*)&Ps[srow][ssub * 4];
            float mx = fmaxf(fmaxf(pv.x, pv.y), fmaxf(pv.z, pv.w));
#pragma unroll
            for (int off = 4; off >= 1; off >>= 1)
                mx = fmaxf(mx, __shfl_xor_sync(0xffffffffu, mx, off));
            mx = fmaxf(mx, m_old);
            pv.x = __expf(pv.x - mx); pv.y = __expf(pv.y - mx);
            pv.z = __expf(pv.z - mx); pv.w = __expf(pv.w - mx);
            *(float4*)&Ps[srow][ssub * 4] = pv;
            float lsum = pv.x + pv.y + pv.z + pv.w;
#pragma unroll
            for (int off = 4; off >= 1; off >>= 1)
                lsum += __shfl_xor_sync(0xffffffffu, lsum, off);
            if (ssub == 0) {
                float c = __expf(m_old - mx);
                l_sh[srow] = l_sh[srow] * c + lsum;
                m_sh[srow] = mx;
                corr_sh[srow] = c;
            }
        }
        __syncthreads();

        // PV accumulate (packed over k pairs)
        {
            const int q = lane;
            const float c = corr_sh[q];
            ull cp = pack2(c, c);
#pragma unroll
            for (int i = 0; i < 11; i++) mul2(acc2[i], acc2[i], cp);
#pragma unroll
            for (int k4 = 0; k4 < 8; k4++) {
                ulonglong2 pp = *(const ulonglong2*)&Ps[q][k4 * 4];
#pragma unroll
                for (int i = 0; i < 11; i++) {
                    ulonglong2 vv = *(const ulonglong2*)&VsT[dbase + i][k4 * 4];
                    fma2(acc2[i], pp.x, vv.x);
                    fma2(acc2[i], pp.y, vv.y);
                }
            }
        }
        __syncthreads();
    }

    {
        const int q = lane;
        int s = q0 + q;
        if (s < SEQ_) {
            float inv = 1.f / l_sh[q];
#pragma unroll
            for (int i = 0; i < 11; i++) {
                float lo, hi; unpack2(acc2[i], lo, hi);
                O[(((size_t)b * SEQ_ + s) * H_ + h) * HD_ + dbase + i] = (lo + hi) * inv;
            }
        }
    }
}

// ---------------------------------------------------------------------------
extern "C" void kernel_launch(void* const* d_in, const int* in_sizes, int n_in,
                              void* d_out, int out_size)
{
    const float* X  = (const float*)d_in[0];
    const float* wq = (const float*)d_in[1];
    const float* bq = (const float*)d_in[2];
    const float* wk = (const float*)d_in[3];
    const float* bk = (const float*)d_in[4];
    const float* wv = (const float*)d_in[5];
    const float* bv = (const float*)d_in[6];
    const float* wo = (const float*)d_in[7];
    const float* bo = (const float*)d_in[8];
    float* out = (float*)d_out;

    float *Qp, *Kp, *Vp, *Cp;
    cudaGetSymbolAddress((void**)&Qp, g_Q);
    cudaGetSymbolAddress((void**)&Kp, g_K);
    cudaGetSymbolAddress((void**)&Vp, g_V);
    cudaGetSymbolAddress((void**)&Cp, g_C);

    cudaFuncSetAttribute(gemm_f32x2_kernel,
                         cudaFuncAttributeMaxDynamicSharedMemorySize, GSMEM);

    dim3 ggrid(D_ / BN, (M_ + BM - 1) / BM);   // (11, 145)

    gemm_f32x2_kernel<<<ggrid, 256, GSMEM>>>(X, wq, bq, Qp, M_);
    gemm_f32x2_kernel<<<ggrid, 256, GSMEM>>>(X, wk, bk, Kp, M_);
    gemm_f32x2_kernel<<<ggrid, 256, GSMEM>>>(X, wv, bv, Vp, M_);

    rope_init_kernel<<<(SEQ_ * 44 + 255) / 256, 256>>>();
    const int rp = B_ * SEQ_ * H_ * 44;
    rope_apply_kernel<<<(rp + 255) / 256, 256>>>();

    dim3 agrid((SEQ_ + 31) / 32, H_, B_);
    attn_kernel<<<agrid, 256>>>(Qp, Kp, Vp, Cp);

    gemm_f32x2_kernel<<<ggrid, 256, GSMEM>>>(Cp, wo, bo, out, M_);
}

// round 7
// speedup vs baseline: 1.8458x; 1.8458x over previous
#include <cuda_runtime.h>
#include <cuda_fp16.h>
#include <math.h>
#include <stdint.h>

// Problem constants
#define B_   32
#define SEQ_ 577
#define H_   16
#define HD_  88
#define D_   1408
#define IDX_ 24
#define M_   (B_ * SEQ_)   // 18464

// Scratch (device globals)
__device__ float  g_Q[(size_t)M_ * D_];
__device__ float  g_K[(size_t)M_ * D_];
__device__ float  g_V[(size_t)M_ * D_];
__device__ float  g_C[(size_t)M_ * D_];
__device__ __half g_Xh[(size_t)M_ * D_];
__device__ __half g_Wh[4][(size_t)D_ * D_];
__device__ float  g_cos[SEQ_ * 44];
__device__ float  g_sin[SEQ_ * 44];

// ---------------------------------------------------------------------------
// helpers
// ---------------------------------------------------------------------------
__device__ __forceinline__ uint32_t smem_u32(const void* p) {
    uint32_t a;
    asm("{ .reg .u64 t; cvta.to.shared.u64 t, %1; cvt.u32.u64 %0, t; }" : "=r"(a) : "l"(p));
    return a;
}
__device__ __forceinline__ void mma_f16(float* d, const uint32_t* a, const uint32_t* b) {
    asm volatile(
        "mma.sync.aligned.m16n8k16.row.col.f32.f16.f16.f32 "
        "{%0,%1,%2,%3},{%4,%5,%6,%7},{%8,%9},{%0,%1,%2,%3};"
        : "+f"(d[0]), "+f"(d[1]), "+f"(d[2]), "+f"(d[3])
        : "r"(a[0]), "r"(a[1]), "r"(a[2]), "r"(a[3]), "r"(b[0]), "r"(b[1]));
}

#define CP_ASYNC(dst, src, sz) \
    asm volatile("cp.async.cg.shared.global [%0], [%1], 16, %2;" \
                 :: "r"(dst), "l"(src), "r"(sz) : "memory")
#define CP_COMMIT() asm volatile("cp.async.commit_group;" ::: "memory")
#define CP_WAIT1()  asm volatile("cp.async.wait_group 1;" ::: "memory")
#define CP_WAIT0()  asm volatile("cp.async.wait_group 0;" ::: "memory")

// ---------------------------------------------------------------------------
// fp32 -> fp16 conversion pass (bandwidth-bound)
// ---------------------------------------------------------------------------
__global__ void f2h_kernel(const float* __restrict__ in,
                           __half* __restrict__ out, int n4)
{
    int i = blockIdx.x * blockDim.x + threadIdx.x;
    if (i >= n4) return;
    float4 v = ((const float4*)in)[i];
    __half2 h0 = __floats2half2_rn(v.x, v.y);
    __half2 h1 = __floats2half2_rn(v.z, v.w);
    ((__half2*)out)[2 * i]     = h0;
    ((__half2*)out)[2 * i + 1] = h1;
}

// ---------------------------------------------------------------------------
// GEMM: C[M][1408] = A[M][1408] @ W[1408][1408]^T + bias  (mma f16, f32 acc)
// A, W pre-converted to fp16. CTA 128x128, BK=64 halfs (128B rows), cp.async
// 2-stage, SW128 XOR swizzle. 8 warps = 2M x 4N, warp tile 64x32.
// ---------------------------------------------------------------------------
constexpr int BM = 128, BN = 128, BKH = 64;
constexpr int NKT = D_ / BKH;             // 22
constexpr int ABYTES = BM * 128;          // 16384 (128 rows x 128B)
constexpr int STG    = 2 * ABYTES;        // 32768
constexpr int GSMEM  = 2 * STG;           // 65536

__global__ __launch_bounds__(256, 2) void gemm_f16_kernel(
    const __half* __restrict__ A, const __half* __restrict__ W,
    const float* __restrict__ bias, float* __restrict__ C, int M)
{
    extern __shared__ __align__(128) char sm[];
    const uint32_t sbase = smem_u32(sm);
    const int t = threadIdx.x, lane = t & 31, wid = t >> 5;
    const int g = lane >> 2, tc = lane & 3;
    const int warpM = wid & 1;     // 0..1 (64 rows)
    const int warpN = wid >> 1;    // 0..3 (32 cols)
    const int bm = blockIdx.y * BM;
    const int bn = blockIdx.x * BN;

    float acc[4][4][4];
#pragma unroll
    for (int mt = 0; mt < 4; mt++)
#pragma unroll
        for (int nt = 0; nt < 4; nt++)
#pragma unroll
            for (int i = 0; i < 4; i++) acc[mt][nt][i] = 0.f;

    auto issue = [&](int kt, int stage) {
        const int k0 = kt * BKH;
        uint32_t dA = sbase + stage * STG;
        uint32_t dB = dA + ABYTES;
#pragma unroll
        for (int i = 0; i < 4; i++) {
            int idx = t + 256 * i;          // 0..1023
            int row = idx >> 3;             // 0..127
            int c4  = idx & 7;              // 16B chunk (8 halfs)
            uint32_t sw = ((uint32_t)row << 7) + ((uint32_t)(c4 ^ (row & 7)) << 4);
            int gm = bm + row;
            const __half* srcA = A + (size_t)(gm < M ? gm : 0) * D_ + k0 + c4 * 8;
            CP_ASYNC(dA + sw, srcA, (gm < M) ? 16 : 0);
            const __half* srcB = W + (size_t)(bn + row) * D_ + k0 + c4 * 8;
            CP_ASYNC(dB + sw, srcB, 16);
        }
        CP_COMMIT();
    };

    issue(0, 0);
    for (int kt = 0; kt < NKT; kt++) {
        const int buf = kt & 1;
        if (kt + 1 < NKT) { issue(kt + 1, buf ^ 1); CP_WAIT1(); }
        else              { CP_WAIT0(); }
        __syncthreads();

        const char* pA = sm + buf * STG;
        const char* pB = pA + ABYTES;

#pragma unroll
        for (int ks = 0; ks < 4; ks++) {
            // k16 step ks covers bytes [32ks, 32ks+32) = chunks 2ks, 2ks+1
            const int swc0 = ((2 * ks)     ^ g) << 4;
            const int swc1 = ((2 * ks + 1) ^ g) << 4;

            uint32_t af[4][4];
#pragma unroll
            for (int mt = 0; mt < 4; mt++) {
                int r0 = warpM * 64 + mt * 16 + g;
                const char* q0 = pA + r0 * 128 + (tc << 2);
                const char* q1 = q0 + 8 * 128;
                af[mt][0] = *(const uint32_t*)(q0 + swc0);
                af[mt][1] = *(const uint32_t*)(q1 + swc0);
                af[mt][2] = *(const uint32_t*)(q0 + swc1);
                af[mt][3] = *(const uint32_t*)(q1 + swc1);
            }
            uint32_t bf[4][2];
#pragma unroll
            for (int nt = 0; nt < 4; nt++) {
                int c0 = warpN * 32 + nt * 8 + g;
                const char* q = pB + c0 * 128 + (tc << 2);
                bf[nt][0] = *(const uint32_t*)(q + swc0);
                bf[nt][1] = *(const uint32_t*)(q + swc1);
            }
#pragma unroll
            for (int mt = 0; mt < 4; mt++)
#pragma unroll
                for (int nt = 0; nt < 4; nt++)
                    mma_f16(acc[mt][nt], af[mt], bf[nt]);
        }
        __syncthreads();
    }

#pragma unroll
    for (int nt = 0; nt < 4; nt++) {
        int c = bn + warpN * 32 + nt * 8 + tc * 2;
        float b0 = bias[c], b1 = bias[c + 1];
#pragma unroll
        for (int mt = 0; mt < 4; mt++) {
            int r0 = bm + warpM * 64 + mt * 16 + g;
            if (r0 < M) {
                float2 v = make_float2(acc[mt][nt][0] + b0, acc[mt][nt][1] + b1);
                *(float2*)&C[(size_t)r0 * D_ + c] = v;
            }
            if (r0 + 8 < M) {
                float2 v = make_float2(acc[mt][nt][2] + b0, acc[mt][nt][3] + b1);
                *(float2*)&C[(size_t)(r0 + 8) * D_ + c] = v;
            }
        }
    }
}

// ---------------------------------------------------------------------------
// Rope tables + apply
// ---------------------------------------------------------------------------
__global__ void rope_init_kernel()
{
    int idx = blockIdx.x * blockDim.x + threadIdx.x;
    if (idx >= SEQ_ * 44) return;
    int s = idx / 44, j = idx % 44;
    double f = 0.0;
    if (s != SEQ_ - 1) {
        int fx = s % IDX_, fy = s / IDX_;
        int i = (j < 22) ? j : j - 22;
        double rf = exp((-2.0 * (double)i / 44.0) * log(10000.0));
        double coord = (j < 22) ? (double)(fx + 1) : (double)(fy + 1);
        f = coord * rf;
    }
    g_cos[idx] = (float)cos(f);
    g_sin[idx] = (float)sin(f);
}

__global__ void rope_apply_kernel()
{
    int idx = blockIdx.x * blockDim.x + threadIdx.x;
    const int total = B_ * SEQ_ * H_ * 44;
    if (idx >= total) return;
    int j    = idx % 44;
    int rest = idx / 44;
    int s    = (rest / H_) % SEQ_;
    size_t base = (size_t)rest * HD_ + 2 * j;
    float c  = g_cos[s * 44 + j];
    float sn = g_sin[s * 44 + j];

    float a = g_Q[base], b = g_Q[base + 1];
    g_Q[base]     = a * c - b * sn;
    g_Q[base + 1] = a * sn + b * c;
    a = g_K[base]; b = g_K[base + 1];
    g_K[base]     = a * c - b * sn;
    g_K[base + 1] = a * sn + b * c;
}

// ---------------------------------------------------------------------------
// Flash attention (fp32 SIMT, parallel softmax) — R5 version.
// ---------------------------------------------------------------------------
__global__ __launch_bounds__(256) void attn_kernel(
    const float* __restrict__ Q, const float* __restrict__ K,
    const float* __restrict__ V, float* __restrict__ O)
{
    const int qt = blockIdx.x, h = blockIdx.y, b = blockIdx.z;
    const int q0 = qt * 32;

    __shared__ __align__(16) float Qs[32][89];
    __shared__ __align__(16) float Ks[32][92];
    __shared__ __align__(16) float VsT[HD_][36];
    __shared__ __align__(16) float Ps[32][36];
    __shared__ float m_sh[32], l_sh[32], corr_sh[32];

    const int t    = threadIdx.x;
    const int lane = t & 31;
    const int warp = t >> 5;
    const int dbase = warp * 11;
    const int srow = t >> 3;
    const int ssub = t & 7;

    for (int idx = t; idx < 32 * HD_; idx += 256) {
        int qq = idx / HD_, d = idx % HD_;
        int s = q0 + qq;
        Qs[qq][d] = (s < SEQ_) ? Q[(((size_t)b * SEQ_ + s) * H_ + h) * HD_ + d] : 0.f;
    }
    if (t < 32) { m_sh[t] = -1e30f; l_sh[t] = 0.f; }
    __syncthreads();

    float qreg[HD_];
#pragma unroll
    for (int d = 0; d < HD_; d++) qreg[d] = Qs[lane][d];

    float acc[11];
#pragma unroll
    for (int i = 0; i < 11; i++) acc[i] = 0.f;

    const float scale = 0.10660035817780521f;

    for (int k0 = 0; k0 < SEQ_; k0 += 32) {
        for (int idx = t; idx < 32 * HD_; idx += 256) {
            int kk = idx / HD_, d = idx % HD_;
            int s = k0 + kk;
            float kv = 0.f, vv = 0.f;
            if (s < SEQ_) {
                size_t gg = (((size_t)b * SEQ_ + s) * H_ + h) * HD_ + d;
                kv = K[gg]; vv = V[gg];
            }
            Ks[kk][d]  = kv;
            VsT[d][kk] = vv;
        }
        __syncthreads();

        {
            const int q = lane;
#pragma unroll
            for (int j = 0; j < 4; j++) {
                int kk = warp * 4 + j;
                float s = 0.f;
#pragma unroll
                for (int d4 = 0; d4 < HD_; d4 += 4) {
                    float4 kv = *(const float4*)&Ks[kk][d4];
                    s += qreg[d4] * kv.x + qreg[d4 + 1] * kv.y
                       + qreg[d4 + 2] * kv.z + qreg[d4 + 3] * kv.w;
                }
                Ps[q][kk] = (k0 + kk < SEQ_) ? s * scale : -1e30f;
            }
        }
        __syncthreads();

        {
            float m_old = m_sh[srow];
            float4 pv = *(const float4*)&Ps[srow][ssub * 4];
            float mx = fmaxf(fmaxf(pv.x, pv.y), fmaxf(pv.z, pv.w));
#pragma unroll
            for (int off = 4; off >= 1; off >>= 1)
                mx = fmaxf(mx, __shfl_xor_sync(0xffffffffu, mx, off));
            mx = fmaxf(mx, m_old);
            pv.x = __expf(pv.x - mx); pv.y = __expf(pv.y - mx);
            pv.z = __expf(pv.z - mx); pv.w = __expf(pv.w - mx);
            *(float4*)&Ps[srow][ssub * 4] = pv;
            float lsum = pv.x + pv.y + pv.z + pv.w;
#pragma unroll
            for (int off = 4; off >= 1; off >>= 1)
                lsum += __shfl_xor_sync(0xffffffffu, lsum, off);
            if (ssub == 0) {
                float c = __expf(m_old - mx);
                l_sh[srow] = l_sh[srow] * c + lsum;
                m_sh[srow] = mx;
                corr_sh[srow] = c;
            }
        }
        __syncthreads();

        {
            const int q = lane;
            const float c = corr_sh[q];
#pragma unroll
            for (int i = 0; i < 11; i++) acc[i] *= c;
#pragma unroll
            for (int k4 = 0; k4 < 32; k4 += 4) {
                float4 p4 = *(const float4*)&Ps[q][k4];
#pragma unroll
                for (int i = 0; i < 11; i++) {
                    float4 v4 = *(const float4*)&VsT[dbase + i][k4];
                    acc[i] += p4.x * v4.x + p4.y * v4.y + p4.z * v4.z + p4.w * v4.w;
                }
            }
        }
        __syncthreads();
    }

    {
        const int q = lane;
        int s = q0 + q;
        if (s < SEQ_) {
            float inv = 1.f / l_sh[q];
#pragma unroll
            for (int i = 0; i < 11; i++) {
                O[(((size_t)b * SEQ_ + s) * H_ + h) * HD_ + dbase + i] = acc[i] * inv;
            }
        }
    }
}

// ---------------------------------------------------------------------------
extern "C" void kernel_launch(void* const* d_in, const int* in_sizes, int n_in,
                              void* d_out, int out_size)
{
    const float* X  = (const float*)d_in[0];
    const float* wq = (const float*)d_in[1];
    const float* bq = (const float*)d_in[2];
    const float* wk = (const float*)d_in[3];
    const float* bk = (const float*)d_in[4];
    const float* wv = (const float*)d_in[5];
    const float* bv = (const float*)d_in[6];
    const float* wo = (const float*)d_in[7];
    const float* bo = (const float*)d_in[8];
    float* out = (float*)d_out;

    float *Qp, *Kp, *Vp, *Cp;
    __half *Xh, *Wh;
    cudaGetSymbolAddress((void**)&Qp, g_Q);
    cudaGetSymbolAddress((void**)&Kp, g_K);
    cudaGetSymbolAddress((void**)&Vp, g_V);
    cudaGetSymbolAddress((void**)&Cp, g_C);
    cudaGetSymbolAddress((void**)&Xh, g_Xh);
    cudaGetSymbolAddress((void**)&Wh, g_Wh);

    cudaFuncSetAttribute(gemm_f16_kernel,
                         cudaFuncAttributeMaxDynamicSharedMemorySize, GSMEM);

    const int WN4 = D_ * D_ / 4;
    const int XN4 = M_ * D_ / 4;
    f2h_kernel<<<(XN4 + 255) / 256, 256>>>(X,  Xh, XN4);
    f2h_kernel<<<(WN4 + 255) / 256, 256>>>(wq, Wh + 0 * (size_t)D_ * D_, WN4);
    f2h_kernel<<<(WN4 + 255) / 256, 256>>>(wk, Wh + 1 * (size_t)D_ * D_, WN4);
    f2h_kernel<<<(WN4 + 255) / 256, 256>>>(wv, Wh + 2 * (size_t)D_ * D_, WN4);
    f2h_kernel<<<(WN4 + 255) / 256, 256>>>(wo, Wh + 3 * (size_t)D_ * D_, WN4);

    dim3 ggrid(D_ / BN, (M_ + BM - 1) / BM);   // (11, 145)

    gemm_f16_kernel<<<ggrid, 256, GSMEM>>>(Xh, Wh + 0 * (size_t)D_ * D_, bq, Qp, M_);
    gemm_f16_kernel<<<ggrid, 256, GSMEM>>>(Xh, Wh + 1 * (size_t)D_ * D_, bk, Kp, M_);
    gemm_f16_kernel<<<ggrid, 256, GSMEM>>>(Xh, Wh + 2 * (size_t)D_ * D_, bv, Vp, M_);

    rope_init_kernel<<<(SEQ_ * 44 + 255) / 256, 256>>>();
    const int rp = B_ * SEQ_ * H_ * 44;
    rope_apply_kernel<<<(rp + 255) / 256, 256>>>();

    dim3 agrid((SEQ_ + 31) / 32, H_, B_);
    attn_kernel<<<agrid, 256>>>(Qp, Kp, Vp, Cp);

    f2h_kernel<<<(XN4 + 255) / 256, 256>>>(Cp, Xh, XN4);
    gemm_f16_kernel<<<ggrid, 256, GSMEM>>>(Xh, Wh + 3 * (size_t)D_ * D_, bo, out, M_);
}

// round 8
// speedup vs baseline: 8.7977x; 4.7664x over previous
#include <cuda_runtime.h>
#include <cuda_fp16.h>
#include <math.h>
#include <stdint.h>

// Problem constants
#define B_   32
#define SEQ_ 577
#define H_   16
#define HD_  88
#define D_   1408
#define IDX_ 24
#define M_   (B_ * SEQ_)   // 18464

// Scratch (device globals)
__device__ __half g_Qh[(size_t)M_ * D_];
__device__ __half g_Kh[(size_t)M_ * D_];
__device__ __half g_Vh[(size_t)M_ * D_];
__device__ __half g_Xh[(size_t)M_ * D_];
__device__ __half g_Wh[4][(size_t)D_ * D_];
__device__ float  g_cos[SEQ_ * 44];
__device__ float  g_sin[SEQ_ * 44];

// ---------------------------------------------------------------------------
// helpers
// ---------------------------------------------------------------------------
__device__ __forceinline__ uint32_t smem_u32(const void* p) {
    uint32_t a;
    asm("{ .reg .u64 t; cvta.to.shared.u64 t, %1; cvt.u32.u64 %0, t; }" : "=r"(a) : "l"(p));
    return a;
}
__device__ __forceinline__ void mma_f16(float* d, const uint32_t* a, const uint32_t* b) {
    asm volatile(
        "mma.sync.aligned.m16n8k16.row.col.f32.f16.f16.f32 "
        "{%0,%1,%2,%3},{%4,%5,%6,%7},{%8,%9},{%0,%1,%2,%3};"
        : "+f"(d[0]), "+f"(d[1]), "+f"(d[2]), "+f"(d[3])
        : "r"(a[0]), "r"(a[1]), "r"(a[2]), "r"(a[3]), "r"(b[0]), "r"(b[1]));
}
__device__ __forceinline__ uint32_t packh2(float lo, float hi) {
    __half2 h = __floats2half2_rn(lo, hi);
    return *(uint32_t*)&h;
}

#define CP_ASYNC(dst, src, sz) \
    asm volatile("cp.async.cg.shared.global [%0], [%1], 16, %2;" \
                 :: "r"(dst), "l"(src), "r"(sz) : "memory")
#define CP_COMMIT() asm volatile("cp.async.commit_group;" ::: "memory")
#define CP_WAIT1()  asm volatile("cp.async.wait_group 1;" ::: "memory")
#define CP_WAIT0()  asm volatile("cp.async.wait_group 0;" ::: "memory")

// ---------------------------------------------------------------------------
// fp32 -> fp16 conversion (for X and the 4 weight matrices)
// ---------------------------------------------------------------------------
__global__ void f2h_kernel(const float* __restrict__ in,
                           __half* __restrict__ out, int n4)
{
    int i = blockIdx.x * blockDim.x + threadIdx.x;
    if (i >= n4) return;
    float4 v = ((const float4*)in)[i];
    ((__half2*)out)[2 * i]     = __floats2half2_rn(v.x, v.y);
    ((__half2*)out)[2 * i + 1] = __floats2half2_rn(v.z, v.w);
}

// ---------------------------------------------------------------------------
// GEMM: C[M][1408] = A[M][1408] @ W[1408][1408]^T + bias  (mma f16, f32 acc)
// Output fp16 (HALF_OUT) or fp32. CTA 128x128, BK=64 halfs, cp.async 2-stage,
// SW128 XOR swizzle. 8 warps = 2M x 4N, warp tile 64x32.
// ---------------------------------------------------------------------------
constexpr int BM = 128, BN = 128, BKH = 64;
constexpr int NKT = D_ / BKH;             // 22
constexpr int ABYTES = BM * 128;          // 16384
constexpr int STG    = 2 * ABYTES;        // 32768
constexpr int GSMEM  = 2 * STG;           // 65536

template <bool HALF_OUT>
__global__ __launch_bounds__(256, 2) void gemm_f16_kernel(
    const __half* __restrict__ A, const __half* __restrict__ W,
    const float* __restrict__ bias, void* __restrict__ Cv, int M)
{
    extern __shared__ __align__(128) char sm[];
    const uint32_t sbase = smem_u32(sm);
    const int t = threadIdx.x, lane = t & 31, wid = t >> 5;
    const int g = lane >> 2, tc = lane & 3;
    const int warpM = wid & 1;
    const int warpN = wid >> 1;
    const int bm = blockIdx.y * BM;
    const int bn = blockIdx.x * BN;

    float acc[4][4][4];
#pragma unroll
    for (int mt = 0; mt < 4; mt++)
#pragma unroll
        for (int nt = 0; nt < 4; nt++)
#pragma unroll
            for (int i = 0; i < 4; i++) acc[mt][nt][i] = 0.f;

    auto issue = [&](int kt, int stage) {
        const int k0 = kt * BKH;
        uint32_t dA = sbase + stage * STG;
        uint32_t dB = dA + ABYTES;
#pragma unroll
        for (int i = 0; i < 4; i++) {
            int idx = t + 256 * i;
            int row = idx >> 3;
            int c4  = idx & 7;
            uint32_t sw = ((uint32_t)row << 7) + ((uint32_t)(c4 ^ (row & 7)) << 4);
            int gm = bm + row;
            const __half* srcA = A + (size_t)(gm < M ? gm : 0) * D_ + k0 + c4 * 8;
            CP_ASYNC(dA + sw, srcA, (gm < M) ? 16 : 0);
            const __half* srcB = W + (size_t)(bn + row) * D_ + k0 + c4 * 8;
            CP_ASYNC(dB + sw, srcB, 16);
        }
        CP_COMMIT();
    };

    issue(0, 0);
    for (int kt = 0; kt < NKT; kt++) {
        const int buf = kt & 1;
        if (kt + 1 < NKT) { issue(kt + 1, buf ^ 1); CP_WAIT1(); }
        else              { CP_WAIT0(); }
        __syncthreads();

        const char* pA = sm + buf * STG;
        const char* pB = pA + ABYTES;

#pragma unroll
        for (int ks = 0; ks < 4; ks++) {
            const int swc0 = ((2 * ks)     ^ g) << 4;
            const int swc1 = ((2 * ks + 1) ^ g) << 4;

            uint32_t af[4][4];
#pragma unroll
            for (int mt = 0; mt < 4; mt++) {
                int r0 = warpM * 64 + mt * 16 + g;
                const char* q0 = pA + r0 * 128 + (tc << 2);
                const char* q1 = q0 + 8 * 128;
                af[mt][0] = *(const uint32_t*)(q0 + swc0);
                af[mt][1] = *(const uint32_t*)(q1 + swc0);
                af[mt][2] = *(const uint32_t*)(q0 + swc1);
                af[mt][3] = *(const uint32_t*)(q1 + swc1);
            }
            uint32_t bf[4][2];
#pragma unroll
            for (int nt = 0; nt < 4; nt++) {
                int c0 = warpN * 32 + nt * 8 + g;
                const char* q = pB + c0 * 128 + (tc << 2);
                bf[nt][0] = *(const uint32_t*)(q + swc0);
                bf[nt][1] = *(const uint32_t*)(q + swc1);
            }
#pragma unroll
            for (int mt = 0; mt < 4; mt++)
#pragma unroll
                for (int nt = 0; nt < 4; nt++)
                    mma_f16(acc[mt][nt], af[mt], bf[nt]);
        }
        __syncthreads();
    }

#pragma unroll
    for (int nt = 0; nt < 4; nt++) {
        int c = bn + warpN * 32 + nt * 8 + tc * 2;
        float b0 = bias[c], b1 = bias[c + 1];
#pragma unroll
        for (int mt = 0; mt < 4; mt++) {
            int r0 = bm + warpM * 64 + mt * 16 + g;
            if (HALF_OUT) {
                __half* C = (__half*)Cv;
                if (r0 < M)
                    *(__half2*)&C[(size_t)r0 * D_ + c] =
                        __floats2half2_rn(acc[mt][nt][0] + b0, acc[mt][nt][1] + b1);
                if (r0 + 8 < M)
                    *(__half2*)&C[(size_t)(r0 + 8) * D_ + c] =
                        __floats2half2_rn(acc[mt][nt][2] + b0, acc[mt][nt][3] + b1);
            } else {
                float* C = (float*)Cv;
                if (r0 < M)
                    *(float2*)&C[(size_t)r0 * D_ + c] =
                        make_float2(acc[mt][nt][0] + b0, acc[mt][nt][1] + b1);
                if (r0 + 8 < M)
                    *(float2*)&C[(size_t)(r0 + 8) * D_ + c] =
                        make_float2(acc[mt][nt][2] + b0, acc[mt][nt][3] + b1);
            }
        }
    }
}

// ---------------------------------------------------------------------------
// Rope tables + apply (in-place on fp16 Q/K; Q scaled by 88^-0.5)
// ---------------------------------------------------------------------------
__global__ void rope_init_kernel()
{
    int idx = blockIdx.x * blockDim.x + threadIdx.x;
    if (idx >= SEQ_ * 44) return;
    int s = idx / 44, j = idx % 44;
    double f = 0.0;
    if (s != SEQ_ - 1) {
        int fx = s % IDX_, fy = s / IDX_;
        int i = (j < 22) ? j : j - 22;
        double rf = exp((-2.0 * (double)i / 44.0) * log(10000.0));
        double coord = (j < 22) ? (double)(fx + 1) : (double)(fy + 1);
        f = coord * rf;
    }
    g_cos[idx] = (float)cos(f);
    g_sin[idx] = (float)sin(f);
}

__global__ void rope_h_kernel()
{
    int idx = blockIdx.x * blockDim.x + threadIdx.x;
    const int total = B_ * SEQ_ * H_ * 44;
    if (idx >= total) return;
    int j    = idx % 44;
    int rest = idx / 44;                 // (b*SEQ + s)*H + h
    int s    = (rest / H_) % SEQ_;
    size_t base = (size_t)rest * HD_ + 2 * j;
    float c  = g_cos[s * 44 + j];
    float sn = g_sin[s * 44 + j];
    const float scale = 0.10660035817780521f;   // 88^-0.5 folded into Q

    __half2 q = *(__half2*)&g_Qh[base];
    float a = __half2float(q.x), b = __half2float(q.y);
    *(__half2*)&g_Qh[base] =
        __floats2half2_rn((a * c - b * sn) * scale, (a * sn + b * c) * scale);

    __half2 k = *(__half2*)&g_Kh[base];
    a = __half2float(k.x); b = __half2float(k.y);
    *(__half2*)&g_Kh[base] =
        __floats2half2_rn(a * c - b * sn, a * sn + b * c);
}

// ---------------------------------------------------------------------------
// Fused flash attention on mma.f16. Block = (b, h, 128 queries), 8 warps,
// each warp owns 16 query rows. Warp-local fragment softmax; P stays in
// registers between the score mma and the PV mma. Output fp16 into g_Xh.
// ---------------------------------------------------------------------------
#define QT   128
#define KT   32
#define QSTR 100   // halfs per Q/K smem row (88 data + 8 zero pad + 4 spare)
#define VSTR 36    // halfs per VsT row (32 data + 4 pad)

__global__ __launch_bounds__(256) void attn_mma_kernel(
    const __half* __restrict__ Q, const __half* __restrict__ K,
    const __half* __restrict__ V, __half* __restrict__ O)
{
    __shared__ __align__(16) __half Qs[QT * QSTR];
    __shared__ __align__(16) __half Ks[KT * QSTR];
    __shared__ __align__(16) __half Vs[HD_ * VSTR];

    const int qt = blockIdx.x, h = blockIdx.y, b = blockIdx.z;
    const int q0 = qt * QT;
    const int t = threadIdx.x, lane = t & 31, wid = t >> 5;
    const int g = lane >> 2, tc = lane & 3;

    // ---- stage Q tile (zero-padded to 96 halfs/row) ----
    for (int idx = t; idx < QT * 24; idx += 256) {
        int r = idx / 24, c = idx % 24;
        int s = q0 + r; if (s >= SEQ_) s = SEQ_ - 1;
        uint2 v = make_uint2(0u, 0u);
        if (c < 22)
            v = *(const uint2*)&Q[(((size_t)b * SEQ_ + s) * H_ + h) * HD_ + c * 4];
        *(uint2*)&Qs[r * QSTR + c * 4] = v;
    }
    __syncthreads();

    // ---- hoist Q fragments (fixed for whole block) ----
    const int rw = wid * 16;
    uint32_t qf[6][4];
#pragma unroll
    for (int ks = 0; ks < 6; ks++) {
        const __half* p0 = &Qs[(rw + g) * QSTR + ks * 16 + 2 * tc];
        const __half* p1 = p0 + 8 * QSTR;
        qf[ks][0] = *(const uint32_t*)p0;
        qf[ks][1] = *(const uint32_t*)p1;
        qf[ks][2] = *(const uint32_t*)(p0 + 8);
        qf[ks][3] = *(const uint32_t*)(p1 + 8);
    }
    __syncthreads();   // Qs no longer needed in smem

    float oacc[11][4];
#pragma unroll
    for (int nt = 0; nt < 11; nt++)
#pragma unroll
        for (int i = 0; i < 4; i++) oacc[nt][i] = 0.f;
    float m0 = -1e30f, m1 = -1e30f, l0 = 0.f, l1 = 0.f;

    for (int k0 = 0; k0 < SEQ_; k0 += KT) {
        // ---- stage K tile ----
        for (int idx = t; idx < KT * 24; idx += 256) {
            int r = idx / 24, c = idx % 24;
            int s = k0 + r;
            uint2 v = make_uint2(0u, 0u);
            if (s < SEQ_ && c < 22)
                v = *(const uint2*)&K[(((size_t)b * SEQ_ + s) * H_ + h) * HD_ + c * 4];
            *(uint2*)&Ks[r * QSTR + c * 4] = v;
        }
        // ---- stage V transposed ----
        for (int idx = t; idx < KT * 22; idx += 256) {
            int r = idx / 22, c = idx % 22;
            int s = k0 + r;
            uint2 v = make_uint2(0u, 0u);
            if (s < SEQ_)
                v = *(const uint2*)&V[(((size_t)b * SEQ_ + s) * H_ + h) * HD_ + c * 4];
            __half h4[4];
            *(uint2*)h4 = v;
#pragma unroll
            for (int j = 0; j < 4; j++)
                Vs[(c * 4 + j) * VSTR + r] = h4[j];
        }
        __syncthreads();

        // ---- scores S(16x32) per warp ----
        float sc[4][4];
#pragma unroll
        for (int nt = 0; nt < 4; nt++)
#pragma unroll
            for (int i = 0; i < 4; i++) sc[nt][i] = 0.f;

#pragma unroll
        for (int ks = 0; ks < 6; ks++) {
#pragma unroll
            for (int nt = 0; nt < 4; nt++) {
                const __half* p = &Ks[(nt * 8 + g) * QSTR + ks * 16 + 2 * tc];
                uint32_t bf[2];
                bf[0] = *(const uint32_t*)p;
                bf[1] = *(const uint32_t*)(p + 8);
                mma_f16(sc[nt], qf[ks], bf);
            }
        }

        // mask invalid keys (only on the last tile)
        if (k0 + KT > SEQ_) {
#pragma unroll
            for (int nt = 0; nt < 4; nt++) {
                int kidx = k0 + nt * 8 + 2 * tc;
                if (kidx >= SEQ_)     { sc[nt][0] = -1e30f; sc[nt][2] = -1e30f; }
                if (kidx + 1 >= SEQ_) { sc[nt][1] = -1e30f; sc[nt][3] = -1e30f; }
            }
        }

        // ---- online softmax (warp-local, quad shfl) ----
        float mx0 = sc[0][0], mx1 = sc[0][2];
#pragma unroll
        for (int nt = 0; nt < 4; nt++) {
            mx0 = fmaxf(mx0, fmaxf(sc[nt][0], sc[nt][1]));
            mx1 = fmaxf(mx1, fmaxf(sc[nt][2], sc[nt][3]));
        }
        mx0 = fmaxf(mx0, __shfl_xor_sync(0xffffffffu, mx0, 1));
        mx0 = fmaxf(mx0, __shfl_xor_sync(0xffffffffu, mx0, 2));
        mx1 = fmaxf(mx1, __shfl_xor_sync(0xffffffffu, mx1, 1));
        mx1 = fmaxf(mx1, __shfl_xor_sync(0xffffffffu, mx1, 2));
        mx0 = fmaxf(mx0, m0); mx1 = fmaxf(mx1, m1);
        float corr0 = __expf(m0 - mx0), corr1 = __expf(m1 - mx1);
        m0 = mx0; m1 = mx1;

        float s0 = 0.f, s1 = 0.f;
#pragma unroll
        for (int nt = 0; nt < 4; nt++) {
            sc[nt][0] = __expf(sc[nt][0] - m0);
            sc[nt][1] = __expf(sc[nt][1] - m0);
            sc[nt][2] = __expf(sc[nt][2] - m1);
            sc[nt][3] = __expf(sc[nt][3] - m1);
            s0 += sc[nt][0] + sc[nt][1];
            s1 += sc[nt][2] + sc[nt][3];
        }
        s0 += __shfl_xor_sync(0xffffffffu, s0, 1);
        s0 += __shfl_xor_sync(0xffffffffu, s0, 2);
        s1 += __shfl_xor_sync(0xffffffffu, s1, 1);
        s1 += __shfl_xor_sync(0xffffffffu, s1, 2);
        l0 = l0 * corr0 + s0;
        l1 = l1 * corr1 + s1;

#pragma unroll
        for (int nt = 0; nt < 11; nt++) {
            oacc[nt][0] *= corr0; oacc[nt][1] *= corr0;
            oacc[nt][2] *= corr1; oacc[nt][3] *= corr1;
        }

        // ---- P (fp16) directly in A-fragment layout ----
        uint32_t pf[2][4];
#pragma unroll
        for (int kv = 0; kv < 2; kv++) {
            pf[kv][0] = packh2(sc[2 * kv][0],     sc[2 * kv][1]);
            pf[kv][1] = packh2(sc[2 * kv][2],     sc[2 * kv][3]);
            pf[kv][2] = packh2(sc[2 * kv + 1][0], sc[2 * kv + 1][1]);
            pf[kv][3] = packh2(sc[2 * kv + 1][2], sc[2 * kv + 1][3]);
        }

        // ---- PV ----
#pragma unroll
        for (int kv = 0; kv < 2; kv++) {
#pragma unroll
            for (int nt = 0; nt < 11; nt++) {
                const __half* p = &Vs[(nt * 8 + g) * VSTR + kv * 16 + 2 * tc];
                uint32_t bf[2];
                bf[0] = *(const uint32_t*)p;
                bf[1] = *(const uint32_t*)(p + 8);
                mma_f16(oacc[nt], pf[kv], bf);
            }
        }
        __syncthreads();
    }

    // ---- epilogue: normalize + fp16 store ----
    float inv0 = 1.f / l0, inv1 = 1.f / l1;
    int s0 = q0 + rw + g, s1 = s0 + 8;
#pragma unroll
    for (int nt = 0; nt < 11; nt++) {
        int d = nt * 8 + 2 * tc;
        if (s0 < SEQ_)
            *(__half2*)&O[(((size_t)b * SEQ_ + s0) * H_ + h) * HD_ + d] =
                __floats2half2_rn(oacc[nt][0] * inv0, oacc[nt][1] * inv0);
        if (s1 < SEQ_)
            *(__half2*)&O[(((size_t)b * SEQ_ + s1) * H_ + h) * HD_ + d] =
                __floats2half2_rn(oacc[nt][2] * inv1, oacc[nt][3] * inv1);
    }
}

// ---------------------------------------------------------------------------
extern "C" void kernel_launch(void* const* d_in, const int* in_sizes, int n_in,
                              void* d_out, int out_size)
{
    const float* X  = (const float*)d_in[0];
    const float* wq = (const float*)d_in[1];
    const float* bq = (const float*)d_in[2];
    const float* wk = (const float*)d_in[3];
    const float* bk = (const float*)d_in[4];
    const float* wv = (const float*)d_in[5];
    const float* bv = (const float*)d_in[6];
    const float* wo = (const float*)d_in[7];
    const float* bo = (const float*)d_in[8];
    float* out = (float*)d_out;

    __half *Qh, *Kh, *Vh, *Xh, *Wh;
    cudaGetSymbolAddress((void**)&Qh, g_Qh);
    cudaGetSymbolAddress((void**)&Kh, g_Kh);
    cudaGetSymbolAddress((void**)&Vh, g_Vh);
    cudaGetSymbolAddress((void**)&Xh, g_Xh);
    cudaGetSymbolAddress((void**)&Wh, g_Wh);

    cudaFuncSetAttribute(gemm_f16_kernel<true>,
                         cudaFuncAttributeMaxDynamicSharedMemorySize, GSMEM);
    cudaFuncSetAttribute(gemm_f16_kernel<false>,
                         cudaFuncAttributeMaxDynamicSharedMemorySize, GSMEM);

    const int WN4 = D_ * D_ / 4;
    const int XN4 = M_ * D_ / 4;
    f2h_kernel<<<(XN4 + 255) / 256, 256>>>(X,  Xh, XN4);
    f2h_kernel<<<(WN4 + 255) / 256, 256>>>(wq, Wh + 0 * (size_t)D_ * D_, WN4);
    f2h_kernel<<<(WN4 + 255) / 256, 256>>>(wk, Wh + 1 * (size_t)D_ * D_, WN4);
    f2h_kernel<<<(WN4 + 255) / 256, 256>>>(wv, Wh + 2 * (size_t)D_ * D_, WN4);
    f2h_kernel<<<(WN4 + 255) / 256, 256>>>(wo, Wh + 3 * (size_t)D_ * D_, WN4);

    dim3 ggrid(D_ / BN, (M_ + BM - 1) / BM);   // (11, 145)

    gemm_f16_kernel<true><<<ggrid, 256, GSMEM>>>(Xh, Wh + 0 * (size_t)D_ * D_, bq, Qh, M_);
    gemm_f16_kernel<true><<<ggrid, 256, GSMEM>>>(Xh, Wh + 1 * (size_t)D_ * D_, bk, Kh, M_);
    gemm_f16_kernel<true><<<ggrid, 256, GSMEM>>>(Xh, Wh + 2 * (size_t)D_ * D_, bv, Vh, M_);

    rope_init_kernel<<<(SEQ_ * 44 + 255) / 256, 256>>>();
    const int rp = B_ * SEQ_ * H_ * 44;
    rope_h_kernel<<<(rp + 255) / 256, 256>>>();

    dim3 agrid((SEQ_ + QT - 1) / QT, H_, B_);  // (5, 16, 32)
    attn_mma_kernel<<<agrid, 256>>>(Qh, Kh, Vh, Xh);

    gemm_f16_kernel<false><<<ggrid, 256, GSMEM>>>(Xh, Wh + 3 * (size_t)D_ * D_, bo, out, M_);
}

// round 10
// speedup vs baseline: 8.9903x; 1.0219x over previous
#include <cuda_runtime.h>
#include <cuda_fp16.h>
#include <math.h>
#include <stdint.h>

// Problem constants
#define B_   32
#define SEQ_ 577
#define H_   16
#define HD_  88
#define D_   1408
#define IDX_ 24
#define M_   (B_ * SEQ_)   // 18464

// Scratch (device globals)
__device__ __half g_Qh[(size_t)M_ * D_];
__device__ __half g_Kh[(size_t)M_ * D_];
__device__ __half g_Vh[(size_t)M_ * D_];
__device__ __half g_Xh[(size_t)M_ * D_];
__device__ __half g_Wh[4][(size_t)D_ * D_];
__device__ float  g_cos[SEQ_ * 44];
__device__ float  g_sin[SEQ_ * 44];

// ---------------------------------------------------------------------------
// helpers
// ---------------------------------------------------------------------------
__device__ __forceinline__ uint32_t smem_u32(const void* p) {
    uint32_t a;
    asm("{ .reg .u64 t; cvta.to.shared.u64 t, %1; cvt.u32.u64 %0, t; }" : "=r"(a) : "l"(p));
    return a;
}
__device__ __forceinline__ void mma_f16(float* d, const uint32_t* a, const uint32_t* b) {
    asm volatile(
        "mma.sync.aligned.m16n8k16.row.col.f32.f16.f16.f32 "
        "{%0,%1,%2,%3},{%4,%5,%6,%7},{%8,%9},{%0,%1,%2,%3};"
        : "+f"(d[0]), "+f"(d[1]), "+f"(d[2]), "+f"(d[3])
        : "r"(a[0]), "r"(a[1]), "r"(a[2]), "r"(a[3]), "r"(b[0]), "r"(b[1]));
}
__device__ __forceinline__ uint32_t packh2(float lo, float hi) {
    __half2 h = __floats2half2_rn(lo, hi);
    return *(uint32_t*)&h;
}

#define CP_ASYNC(dst, src, sz) \
    asm volatile("cp.async.cg.shared.global [%0], [%1], 16, %2;" \
                 :: "r"(dst), "l"(src), "r"(sz) : "memory")
#define CP_COMMIT() asm volatile("cp.async.commit_group;" ::: "memory")
#define CP_WAIT1()  asm volatile("cp.async.wait_group 1;" ::: "memory")
#define CP_WAIT0()  asm volatile("cp.async.wait_group 0;" ::: "memory")

// ---------------------------------------------------------------------------
// fp32 -> fp16 conversion
// ---------------------------------------------------------------------------
__global__ void f2h_kernel(const float* __restrict__ in,
                           __half* __restrict__ out, int n4)
{
    int i = blockIdx.x * blockDim.x + threadIdx.x;
    if (i >= n4) return;
    float4 v = ((const float4*)in)[i];
    ((__half2*)out)[2 * i]     = __floats2half2_rn(v.x, v.y);
    ((__half2*)out)[2 * i + 1] = __floats2half2_rn(v.z, v.w);
}

// ---------------------------------------------------------------------------
// Rope tables
// ---------------------------------------------------------------------------
__global__ void rope_init_kernel()
{
    int idx = blockIdx.x * blockDim.x + threadIdx.x;
    if (idx >= SEQ_ * 44) return;
    int s = idx / 44, j = idx % 44;
    double f = 0.0;
    if (s != SEQ_ - 1) {
        int fx = s % IDX_, fy = s / IDX_;
        int i = (j < 22) ? j : j - 22;
        double rf = exp((-2.0 * (double)i / 44.0) * log(10000.0));
        double coord = (j < 22) ? (double)(fx + 1) : (double)(fy + 1);
        f = coord * rf;
    }
    g_cos[idx] = (float)cos(f);
    g_sin[idx] = (float)sin(f);
}

// ---------------------------------------------------------------------------
// GEMM tile config
// ---------------------------------------------------------------------------
constexpr int BM = 128, BN = 128, BKH = 64;
constexpr int NKT = D_ / BKH;             // 22
constexpr int ABYTES = BM * 128;          // 16384
constexpr int STG    = 2 * ABYTES;        // 32768
constexpr int GSMEM  = 2 * STG;           // 65536
constexpr int NBN    = D_ / BN;           // 11

// ---------------------------------------------------------------------------
// Epilogue functors (no extended-lambda support in the harness toolchain)
// ---------------------------------------------------------------------------
struct EpiQKV {
    const float* bias;
    __half* C;
    int which;   // 0=Q 1=K 2=V
    int M;
    __device__ __forceinline__ void operator()(int r, int c, float v0, float v1) const {
        if (r >= M) return;
        v0 += bias[c];
        v1 += bias[c + 1];
        if (which < 2) {
            int s = r % SEQ_;
            int j = (c % HD_) >> 1;               // c is even -> rope pair index
            float cs = g_cos[s * 44 + j];
            float sn = g_sin[s * 44 + j];
            float a = v0, b = v1;
            v0 = a * cs - b * sn;
            v1 = a * sn + b * cs;
            if (which == 0) {
                const float qscale = 0.10660035817780521f;   // 88^-0.5
                v0 *= qscale; v1 *= qscale;
            }
        }
        *(__half2*)&C[(size_t)r * D_ + c] = __floats2half2_rn(v0, v1);
    }
};

struct EpiOut {
    const float* bias;
    float* C;
    int M;
    __device__ __forceinline__ void operator()(int r, int c, float v0, float v1) const {
        if (r >= M) return;
        *(float2*)&C[(size_t)r * D_ + c] =
            make_float2(v0 + bias[c], v1 + bias[c + 1]);
    }
};

// Shared GEMM mainloop body (one 128x128 tile)
template <typename EPI>
__device__ __forceinline__ void gemm_body(
    const __half* __restrict__ A, const __half* __restrict__ W,
    char* sm, int bm, int bn, int M, EPI epilogue)
{
    const uint32_t sbase = smem_u32(sm);
    const int t = threadIdx.x, lane = t & 31, wid = t >> 5;
    const int g = lane >> 2, tc = lane & 3;
    const int warpM = wid & 1;
    const int warpN = wid >> 1;

    float acc[4][4][4];
#pragma unroll
    for (int mt = 0; mt < 4; mt++)
#pragma unroll
        for (int nt = 0; nt < 4; nt++)
#pragma unroll
            for (int i = 0; i < 4; i++) acc[mt][nt][i] = 0.f;

    auto issue = [&](int kt, int stage) {
        const int k0 = kt * BKH;
        uint32_t dA = sbase + stage * STG;
        uint32_t dB = dA + ABYTES;
#pragma unroll
        for (int i = 0; i < 4; i++) {
            int idx = t + 256 * i;
            int row = idx >> 3;
            int c4  = idx & 7;
            uint32_t sw = ((uint32_t)row << 7) + ((uint32_t)(c4 ^ (row & 7)) << 4);
            int gm = bm + row;
            const __half* srcA = A + (size_t)(gm < M ? gm : 0) * D_ + k0 + c4 * 8;
            CP_ASYNC(dA + sw, srcA, (gm < M) ? 16 : 0);
            const __half* srcB = W + (size_t)(bn + row) * D_ + k0 + c4 * 8;
            CP_ASYNC(dB + sw, srcB, 16);
        }
        CP_COMMIT();
    };

    issue(0, 0);
    for (int kt = 0; kt < NKT; kt++) {
        const int buf = kt & 1;
        if (kt + 1 < NKT) { issue(kt + 1, buf ^ 1); CP_WAIT1(); }
        else              { CP_WAIT0(); }
        __syncthreads();

        const char* pA = sm + buf * STG;
        const char* pB = pA + ABYTES;

#pragma unroll
        for (int ks = 0; ks < 4; ks++) {
            const int swc0 = ((2 * ks)     ^ g) << 4;
            const int swc1 = ((2 * ks + 1) ^ g) << 4;

            uint32_t af[4][4];
#pragma unroll
            for (int mt = 0; mt < 4; mt++) {
                int r0 = warpM * 64 + mt * 16 + g;
                const char* q0 = pA + r0 * 128 + (tc << 2);
                const char* q1 = q0 + 8 * 128;
                af[mt][0] = *(const uint32_t*)(q0 + swc0);
                af[mt][1] = *(const uint32_t*)(q1 + swc0);
                af[mt][2] = *(const uint32_t*)(q0 + swc1);
                af[mt][3] = *(const uint32_t*)(q1 + swc1);
            }
            uint32_t bf[4][2];
#pragma unroll
            for (int nt = 0; nt < 4; nt++) {
                int c0 = warpN * 32 + nt * 8 + g;
                const char* q = pB + c0 * 128 + (tc << 2);
                bf[nt][0] = *(const uint32_t*)(q + swc0);
                bf[nt][1] = *(const uint32_t*)(q + swc1);
            }
#pragma unroll
            for (int mt = 0; mt < 4; mt++)
#pragma unroll
                for (int nt = 0; nt < 4; nt++)
                    mma_f16(acc[mt][nt], af[mt], bf[nt]);
        }
        __syncthreads();
    }

#pragma unroll
    for (int nt = 0; nt < 4; nt++) {
        int c = bn + warpN * 32 + nt * 8 + tc * 2;
#pragma unroll
        for (int mt = 0; mt < 4; mt++) {
            int r0 = bm + warpM * 64 + mt * 16 + g;
            epilogue(r0,     c, acc[mt][nt][0], acc[mt][nt][1]);
            epilogue(r0 + 8, c, acc[mt][nt][2], acc[mt][nt][3]);
        }
    }
}

// ---------------------------------------------------------------------------
// Fused QKV GEMM + bias + rope (Q scaled). grid.x = 3*NBN.
// ---------------------------------------------------------------------------
__global__ __launch_bounds__(256, 2) void gemm_qkv_kernel(
    const __half* __restrict__ A, const __half* __restrict__ Wall,
    const float* __restrict__ bq, const float* __restrict__ bk,
    const float* __restrict__ bv, __half* __restrict__ Qh,
    __half* __restrict__ Kh, __half* __restrict__ Vh, int M)
{
    extern __shared__ __align__(128) char sm[];
    const int which = blockIdx.x / NBN;              // 0=Q 1=K 2=V
    const int bn = (blockIdx.x % NBN) * BN;
    const int bm = blockIdx.y * BM;

    const __half* W = Wall + (size_t)which * D_ * D_;
    EpiQKV epi;
    epi.bias  = (which == 0) ? bq : (which == 1) ? bk : bv;
    epi.C     = (which == 0) ? Qh : (which == 1) ? Kh : Vh;
    epi.which = which;
    epi.M     = M;

    gemm_body(A, W, sm, bm, bn, M, epi);
}

// ---------------------------------------------------------------------------
// Plain GEMM + bias, fp32 output (final projection)
// ---------------------------------------------------------------------------
__global__ __launch_bounds__(256, 2) void gemm_out_kernel(
    const __half* __restrict__ A, const __half* __restrict__ W,
    const float* __restrict__ bias, float* __restrict__ C, int M)
{
    extern __shared__ __align__(128) char sm[];
    const int bn = blockIdx.x * BN;
    const int bm = blockIdx.y * BM;

    EpiOut epi; epi.bias = bias; epi.C = C; epi.M = M;
    gemm_body(A, W, sm, bm, bn, M, epi);
}

// ---------------------------------------------------------------------------
// Fused flash attention on mma.f16 (unchanged, proven at R8).
// ---------------------------------------------------------------------------
#define QT   128
#define KT   32
#define QSTR 100
#define VSTR 36

__global__ __launch_bounds__(256) void attn_mma_kernel(
    const __half* __restrict__ Q, const __half* __restrict__ K,
    const __half* __restrict__ V, __half* __restrict__ O)
{
    __shared__ __align__(16) __half Qs[QT * QSTR];
    __shared__ __align__(16) __half Ks[KT * QSTR];
    __shared__ __align__(16) __half Vs[HD_ * VSTR];

    const int qt = blockIdx.x, h = blockIdx.y, b = blockIdx.z;
    const int q0 = qt * QT;
    const int t = threadIdx.x, lane = t & 31, wid = t >> 5;
    const int g = lane >> 2, tc = lane & 3;

    for (int idx = t; idx < QT * 24; idx += 256) {
        int r = idx / 24, c = idx % 24;
        int s = q0 + r; if (s >= SEQ_) s = SEQ_ - 1;
        uint2 v = make_uint2(0u, 0u);
        if (c < 22)
            v = *(const uint2*)&Q[(((size_t)b * SEQ_ + s) * H_ + h) * HD_ + c * 4];
        *(uint2*)&Qs[r * QSTR + c * 4] = v;
    }
    __syncthreads();

    const int rw = wid * 16;
    uint32_t qf[6][4];
#pragma unroll
    for (int ks = 0; ks < 6; ks++) {
        const __half* p0 = &Qs[(rw + g) * QSTR + ks * 16 + 2 * tc];
        const __half* p1 = p0 + 8 * QSTR;
        qf[ks][0] = *(const uint32_t*)p0;
        qf[ks][1] = *(const uint32_t*)p1;
        qf[ks][2] = *(const uint32_t*)(p0 + 8);
        qf[ks][3] = *(const uint32_t*)(p1 + 8);
    }
    __syncthreads();

    float oacc[11][4];
#pragma unroll
    for (int nt = 0; nt < 11; nt++)
#pragma unroll
        for (int i = 0; i < 4; i++) oacc[nt][i] = 0.f;
    float m0 = -1e30f, m1 = -1e30f, l0 = 0.f, l1 = 0.f;

    for (int k0 = 0; k0 < SEQ_; k0 += KT) {
        for (int idx = t; idx < KT * 24; idx += 256) {
            int r = idx / 24, c = idx % 24;
            int s = k0 + r;
            uint2 v = make_uint2(0u, 0u);
            if (s < SEQ_ && c < 22)
                v = *(const uint2*)&K[(((size_t)b * SEQ_ + s) * H_ + h) * HD_ + c * 4];
            *(uint2*)&Ks[r * QSTR + c * 4] = v;
        }
        for (int idx = t; idx < KT * 22; idx += 256) {
            int r = idx / 22, c = idx % 22;
            int s = k0 + r;
            uint2 v = make_uint2(0u, 0u);
            if (s < SEQ_)
                v = *(const uint2*)&V[(((size_t)b * SEQ_ + s) * H_ + h) * HD_ + c * 4];
            __half h4[4];
            *(uint2*)h4 = v;
#pragma unroll
            for (int j = 0; j < 4; j++)
                Vs[(c * 4 + j) * VSTR + r] = h4[j];
        }
        __syncthreads();

        float sc[4][4];
#pragma unroll
        for (int nt = 0; nt < 4; nt++)
#pragma unroll
            for (int i = 0; i < 4; i++) sc[nt][i] = 0.f;

#pragma unroll
        for (int ks = 0; ks < 6; ks++) {
#pragma unroll
            for (int nt = 0; nt < 4; nt++) {
                const __half* p = &Ks[(nt * 8 + g) * QSTR + ks * 16 + 2 * tc];
                uint32_t bf[2];
                bf[0] = *(const uint32_t*)p;
                bf[1] = *(const uint32_t*)(p + 8);
                mma_f16(sc[nt], qf[ks], bf);
            }
        }

        if (k0 + KT > SEQ_) {
#pragma unroll
            for (int nt = 0; nt < 4; nt++) {
                int kidx = k0 + nt * 8 + 2 * tc;
                if (kidx >= SEQ_)     { sc[nt][0] = -1e30f; sc[nt][2] = -1e30f; }
                if (kidx + 1 >= SEQ_) { sc[nt][1] = -1e30f; sc[nt][3] = -1e30f; }
            }
        }

        float mx0 = sc[0][0], mx1 = sc[0][2];
#pragma unroll
        for (int nt = 0; nt < 4; nt++) {
            mx0 = fmaxf(mx0, fmaxf(sc[nt][0], sc[nt][1]));
            mx1 = fmaxf(mx1, fmaxf(sc[nt][2], sc[nt][3]));
        }
        mx0 = fmaxf(mx0, __shfl_xor_sync(0xffffffffu, mx0, 1));
        mx0 = fmaxf(mx0, __shfl_xor_sync(0xffffffffu, mx0, 2));
        mx1 = fmaxf(mx1, __shfl_xor_sync(0xffffffffu, mx1, 1));
        mx1 = fmaxf(mx1, __shfl_xor_sync(0xffffffffu, mx1, 2));
        mx0 = fmaxf(mx0, m0); mx1 = fmaxf(mx1, m1);
        float corr0 = __expf(m0 - mx0), corr1 = __expf(m1 - mx1);
        m0 = mx0; m1 = mx1;

        float s0 = 0.f, s1 = 0.f;
#pragma unroll
        for (int nt = 0; nt < 4; nt++) {
            sc[nt][0] = __expf(sc[nt][0] - m0);
            sc[nt][1] = __expf(sc[nt][1] - m0);
            sc[nt][2] = __expf(sc[nt][2] - m1);
            sc[nt][3] = __expf(sc[nt][3] - m1);
            s0 += sc[nt][0] + sc[nt][1];
            s1 += sc[nt][2] + sc[nt][3];
        }
        s0 += __shfl_xor_sync(0xffffffffu, s0, 1);
        s0 += __shfl_xor_sync(0xffffffffu, s0, 2);
        s1 += __shfl_xor_sync(0xffffffffu, s1, 1);
        s1 += __shfl_xor_sync(0xffffffffu, s1, 2);
        l0 = l0 * corr0 + s0;
        l1 = l1 * corr1 + s1;

#pragma unroll
        for (int nt = 0; nt < 11; nt++) {
            oacc[nt][0] *= corr0; oacc[nt][1] *= corr0;
            oacc[nt][2] *= corr1; oacc[nt][3] *= corr1;
        }

        uint32_t pf[2][4];
#pragma unroll
        for (int kv = 0; kv < 2; kv++) {
            pf[kv][0] = packh2(sc[2 * kv][0],     sc[2 * kv][1]);
            pf[kv][1] = packh2(sc[2 * kv][2],     sc[2 * kv][3]);
            pf[kv][2] = packh2(sc[2 * kv + 1][0], sc[2 * kv + 1][1]);
            pf[kv][3] = packh2(sc[2 * kv + 1][2], sc[2 * kv + 1][3]);
        }

#pragma unroll
        for (int kv = 0; kv < 2; kv++) {
#pragma unroll
            for (int nt = 0; nt < 11; nt++) {
                const __half* p = &Vs[(nt * 8 + g) * VSTR + kv * 16 + 2 * tc];
                uint32_t bf[2];
                bf[0] = *(const uint32_t*)p;
                bf[1] = *(const uint32_t*)(p + 8);
                mma_f16(oacc[nt], pf[kv], bf);
            }
        }
        __syncthreads();
    }

    float inv0 = 1.f / l0, inv1 = 1.f / l1;
    int s0 = q0 + rw + g, s1 = s0 + 8;
#pragma unroll
    for (int nt = 0; nt < 11; nt++) {
        int d = nt * 8 + 2 * tc;
        if (s0 < SEQ_)
            *(__half2*)&O[(((size_t)b * SEQ_ + s0) * H_ + h) * HD_ + d] =
                __floats2half2_rn(oacc[nt][0] * inv0, oacc[nt][1] * inv0);
        if (s1 < SEQ_)
            *(__half2*)&O[(((size_t)b * SEQ_ + s1) * H_ + h) * HD_ + d] =
                __floats2half2_rn(oacc[nt][2] * inv1, oacc[nt][3] * inv1);
    }
}

// ---------------------------------------------------------------------------
extern "C" void kernel_launch(void* const* d_in, const int* in_sizes, int n_in,
                              void* d_out, int out_size)
{
    const float* X  = (const float*)d_in[0];
    const float* wq = (const float*)d_in[1];
    const float* bq = (const float*)d_in[2];
    const float* wk = (const float*)d_in[3];
    const float* bk = (const float*)d_in[4];
    const float* wv = (const float*)d_in[5];
    const float* bv = (const float*)d_in[6];
    const float* wo = (const float*)d_in[7];
    const float* bo = (const float*)d_in[8];
    float* out = (float*)d_out;

    __half *Qh, *Kh, *Vh, *Xh, *Wh;
    cudaGetSymbolAddress((void**)&Qh, g_Qh);
    cudaGetSymbolAddress((void**)&Kh, g_Kh);
    cudaGetSymbolAddress((void**)&Vh, g_Vh);
    cudaGetSymbolAddress((void**)&Xh, g_Xh);
    cudaGetSymbolAddress((void**)&Wh, g_Wh);

    cudaFuncSetAttribute(gemm_qkv_kernel,
                         cudaFuncAttributeMaxDynamicSharedMemorySize, GSMEM);
    cudaFuncSetAttribute(gemm_out_kernel,
                         cudaFuncAttributeMaxDynamicSharedMemorySize, GSMEM);

    const int WN4 = D_ * D_ / 4;
    const int XN4 = M_ * D_ / 4;
    f2h_kernel<<<(XN4 + 255) / 256, 256>>>(X,  Xh, XN4);
    f2h_kernel<<<(WN4 + 255) / 256, 256>>>(wq, Wh + 0 * (size_t)D_ * D_, WN4);
    f2h_kernel<<<(WN4 + 255) / 256, 256>>>(wk, Wh + 1 * (size_t)D_ * D_, WN4);
    f2h_kernel<<<(WN4 + 255) / 256, 256>>>(wv, Wh + 2 * (size_t)D_ * D_, WN4);
    f2h_kernel<<<(WN4 + 255) / 256, 256>>>(wo, Wh + 3 * (size_t)D_ * D_, WN4);
    rope_init_kernel<<<(SEQ_ * 44 + 255) / 256, 256>>>();

    dim3 qgrid(3 * NBN, (M_ + BM - 1) / BM);   // (33, 145)
    gemm_qkv_kernel<<<qgrid, 256, GSMEM>>>(Xh, Wh, bq, bk, bv, Qh, Kh, Vh, M_);

    dim3 agrid((SEQ_ + QT - 1) / QT, H_, B_);  // (5, 16, 32)
    attn_mma_kernel<<<agrid, 256>>>(Qh, Kh, Vh, Xh);

    dim3 ogrid(NBN, (M_ + BM - 1) / BM);       // (11, 145)
    gemm_out_kernel<<<ogrid, 256, GSMEM>>>(Xh, Wh + 3 * (size_t)D_ * D_, bo, out, M_);
}

// round 11
// speedup vs baseline: 9.5653x; 1.0640x over previous
#include <cuda_runtime.h>
#include <cuda_fp16.h>
#include <math.h>
#include <stdint.h>

// Problem constants
#define B_   32
#define SEQ_ 577
#define H_   16
#define HD_  88
#define D_   1408
#define IDX_ 24
#define M_   (B_ * SEQ_)   // 18464

// Scratch (device globals)
__device__ __half g_Qh[(size_t)M_ * D_];
__device__ __half g_Kh[(size_t)M_ * D_];
__device__ __half g_Vh[(size_t)M_ * D_];
__device__ __half g_Xh[(size_t)M_ * D_];
__device__ __half g_Wh[4][(size_t)D_ * D_];
__device__ float  g_cos[SEQ_ * 44];
__device__ float  g_sin[SEQ_ * 44];

// ---------------------------------------------------------------------------
// helpers
// ---------------------------------------------------------------------------
__device__ __forceinline__ uint32_t smem_u32(const void* p) {
    uint32_t a;
    asm("{ .reg .u64 t; cvta.to.shared.u64 t, %1; cvt.u32.u64 %0, t; }" : "=r"(a) : "l"(p));
    return a;
}
__device__ __forceinline__ void mma_f16(float* d, const uint32_t* a, const uint32_t* b) {
    asm volatile(
        "mma.sync.aligned.m16n8k16.row.col.f32.f16.f16.f32 "
        "{%0,%1,%2,%3},{%4,%5,%6,%7},{%8,%9},{%0,%1,%2,%3};"
        : "+f"(d[0]), "+f"(d[1]), "+f"(d[2]), "+f"(d[3])
        : "r"(a[0]), "r"(a[1]), "r"(a[2]), "r"(a[3]), "r"(b[0]), "r"(b[1]));
}
__device__ __forceinline__ void ldsm_x4(uint32_t* r, uint32_t addr) {
    asm volatile("ldmatrix.sync.aligned.m8n8.x4.shared.b16 {%0,%1,%2,%3}, [%4];"
                 : "=r"(r[0]), "=r"(r[1]), "=r"(r[2]), "=r"(r[3]) : "r"(addr));
}
__device__ __forceinline__ uint32_t packh2(float lo, float hi) {
    __half2 h = __floats2half2_rn(lo, hi);
    return *(uint32_t*)&h;
}

#define CP_ASYNC(dst, src, sz) \
    asm volatile("cp.async.cg.shared.global [%0], [%1], 16, %2;" \
                 :: "r"(dst), "l"(src), "r"(sz) : "memory")
#define CP_COMMIT() asm volatile("cp.async.commit_group;" ::: "memory")
#define CP_WAIT1()  asm volatile("cp.async.wait_group 1;" ::: "memory")
#define CP_WAIT0()  asm volatile("cp.async.wait_group 0;" ::: "memory")

// ---------------------------------------------------------------------------
// fp32 -> fp16 conversions (X single, 4 weights in one launch via blockIdx.y)
// ---------------------------------------------------------------------------
__global__ void f2h_kernel(const float* __restrict__ in,
                           __half* __restrict__ out, int n4)
{
    int i = blockIdx.x * blockDim.x + threadIdx.x;
    if (i >= n4) return;
    float4 v = ((const float4*)in)[i];
    ((__half2*)out)[2 * i]     = __floats2half2_rn(v.x, v.y);
    ((__half2*)out)[2 * i + 1] = __floats2half2_rn(v.z, v.w);
}

__global__ void f2h4_kernel(const float* __restrict__ w0, const float* __restrict__ w1,
                            const float* __restrict__ w2, const float* __restrict__ w3,
                            __half* __restrict__ out, int n4)
{
    int i = blockIdx.x * blockDim.x + threadIdx.x;
    if (i >= n4) return;
    const float* in = (blockIdx.y == 0) ? w0 : (blockIdx.y == 1) ? w1
                     : (blockIdx.y == 2) ? w2 : w3;
    __half* o = out + (size_t)blockIdx.y * D_ * D_;
    float4 v = ((const float4*)in)[i];
    ((__half2*)o)[2 * i]     = __floats2half2_rn(v.x, v.y);
    ((__half2*)o)[2 * i + 1] = __floats2half2_rn(v.z, v.w);
}

// ---------------------------------------------------------------------------
// Rope tables
// ---------------------------------------------------------------------------
__global__ void rope_init_kernel()
{
    int idx = blockIdx.x * blockDim.x + threadIdx.x;
    if (idx >= SEQ_ * 44) return;
    int s = idx / 44, j = idx % 44;
    double f = 0.0;
    if (s != SEQ_ - 1) {
        int fx = s % IDX_, fy = s / IDX_;
        int i = (j < 22) ? j : j - 22;
        double rf = exp((-2.0 * (double)i / 44.0) * log(10000.0));
        double coord = (j < 22) ? (double)(fx + 1) : (double)(fy + 1);
        f = coord * rf;
    }
    g_cos[idx] = (float)cos(f);
    g_sin[idx] = (float)sin(f);
}

// ---------------------------------------------------------------------------
// GEMM tile config
// ---------------------------------------------------------------------------
constexpr int BM = 128, BN = 128, BKH = 64;
constexpr int NKT = D_ / BKH;             // 22
constexpr int ABYTES = BM * 128;          // 16384
constexpr int STG    = 2 * ABYTES;        // 32768
constexpr int GSMEM  = 2 * STG;           // 65536
constexpr int NBN    = D_ / BN;           // 11

// ---------------------------------------------------------------------------
// Epilogue functors
// ---------------------------------------------------------------------------
struct EpiQKV {
    const float* bias;
    __half* C;
    int which;   // 0=Q 1=K 2=V
    int M;
    __device__ __forceinline__ void operator()(int r, int c, float v0, float v1) const {
        if (r >= M) return;
        v0 += bias[c];
        v1 += bias[c + 1];
        if (which < 2) {
            int s = r % SEQ_;
            int j = (c % HD_) >> 1;
            float cs = g_cos[s * 44 + j];
            float sn = g_sin[s * 44 + j];
            float a = v0, b = v1;
            v0 = a * cs - b * sn;
            v1 = a * sn + b * cs;
            if (which == 0) {
                const float qscale = 0.10660035817780521f;
                v0 *= qscale; v1 *= qscale;
            }
        }
        *(__half2*)&C[(size_t)r * D_ + c] = __floats2half2_rn(v0, v1);
    }
};

struct EpiOut {
    const float* bias;
    float* C;
    int M;
    __device__ __forceinline__ void operator()(int r, int c, float v0, float v1) const {
        if (r >= M) return;
        *(float2*)&C[(size_t)r * D_ + c] =
            make_float2(v0 + bias[c], v1 + bias[c + 1]);
    }
};

// Shared GEMM mainloop (one 128x128 tile), ldmatrix fragment feed.
template <typename EPI>
__device__ __forceinline__ void gemm_body(
    const __half* __restrict__ A, const __half* __restrict__ W,
    char* sm, int bm, int bn, int M, EPI epilogue)
{
    const uint32_t sbase = smem_u32(sm);
    const int t = threadIdx.x, lane = t & 31, wid = t >> 5;
    const int g = lane >> 2, tc = lane & 3;
    const int lr = lane & 7, grp = lane >> 3;
    const int warpM = wid & 1;
    const int warpN = wid >> 1;

    // ldmatrix row-base offsets (bytes). row&7 == lr for all tiles.
    uint32_t aoff[4], boff[2];
#pragma unroll
    for (int mt = 0; mt < 4; mt++)
        aoff[mt] = (uint32_t)(warpM * 64 + mt * 16 + lr + ((grp & 1) << 3)) << 7;
#pragma unroll
    for (int np = 0; np < 2; np++)
        boff[np] = (uint32_t)(warpN * 32 + np * 16 + lr + ((grp >> 1) << 3)) << 7;
    const int acpar = grp >> 1;   // A chunk parity (m0,m1=ch0; m2,m3=ch1)
    const int bcpar = grp & 1;    // B chunk parity (m0,m2=ch0; m1,m3=ch1)

    float acc[4][4][4];
#pragma unroll
    for (int mt = 0; mt < 4; mt++)
#pragma unroll
        for (int nt = 0; nt < 4; nt++)
#pragma unroll
            for (int i = 0; i < 4; i++) acc[mt][nt][i] = 0.f;

    auto issue = [&](int kt, int stage) {
        const int k0 = kt * BKH;
        uint32_t dA = sbase + stage * STG;
        uint32_t dB = dA + ABYTES;
#pragma unroll
        for (int i = 0; i < 4; i++) {
            int idx = t + 256 * i;
            int row = idx >> 3;
            int c4  = idx & 7;
            uint32_t sw = ((uint32_t)row << 7) + ((uint32_t)(c4 ^ (row & 7)) << 4);
            int gm = bm + row;
            const __half* srcA = A + (size_t)(gm < M ? gm : 0) * D_ + k0 + c4 * 8;
            CP_ASYNC(dA + sw, srcA, (gm < M) ? 16 : 0);
            const __half* srcB = W + (size_t)(bn + row) * D_ + k0 + c4 * 8;
            CP_ASYNC(dB + sw, srcB, 16);
        }
        CP_COMMIT();
    };

    issue(0, 0);
    for (int kt = 0; kt < NKT; kt++) {
        const int buf = kt & 1;
        if (kt + 1 < NKT) { issue(kt + 1, buf ^ 1); CP_WAIT1(); }
        else              { CP_WAIT0(); }
        __syncthreads();

        const uint32_t sA = sbase + buf * STG;
        const uint32_t sB = sA + ABYTES;

#pragma unroll
        for (int ks = 0; ks < 4; ks++) {
            const uint32_t aco = (uint32_t)(((2 * ks + acpar) ^ lr) << 4);
            const uint32_t bco = (uint32_t)(((2 * ks + bcpar) ^ lr) << 4);

            uint32_t af[4][4];
#pragma unroll
            for (int mt = 0; mt < 4; mt++)
                ldsm_x4(af[mt], sA + aoff[mt] + aco);

            uint32_t bf[4][2];
#pragma unroll
            for (int np = 0; np < 2; np++) {
                uint32_t r[4];
                ldsm_x4(r, sB + boff[np] + bco);
                bf[2 * np][0]     = r[0];
                bf[2 * np][1]     = r[1];
                bf[2 * np + 1][0] = r[2];
                bf[2 * np + 1][1] = r[3];
            }
#pragma unroll
            for (int mt = 0; mt < 4; mt++)
#pragma unroll
                for (int nt = 0; nt < 4; nt++)
                    mma_f16(acc[mt][nt], af[mt], bf[nt]);
        }
        __syncthreads();
    }

#pragma unroll
    for (int nt = 0; nt < 4; nt++) {
        int c = bn + warpN * 32 + nt * 8 + tc * 2;
#pragma unroll
        for (int mt = 0; mt < 4; mt++) {
            int r0 = bm + warpM * 64 + mt * 16 + g;
            epilogue(r0,     c, acc[mt][nt][0], acc[mt][nt][1]);
            epilogue(r0 + 8, c, acc[mt][nt][2], acc[mt][nt][3]);
        }
    }
}

// ---------------------------------------------------------------------------
// Fused QKV GEMM + bias + rope (Q scaled). grid.x = 3*NBN.
// ---------------------------------------------------------------------------
__global__ __launch_bounds__(256, 2) void gemm_qkv_kernel(
    const __half* __restrict__ A, const __half* __restrict__ Wall,
    const float* __restrict__ bq, const float* __restrict__ bk,
    const float* __restrict__ bv, __half* __restrict__ Qh,
    __half* __restrict__ Kh, __half* __restrict__ Vh, int M)
{
    extern __shared__ __align__(128) char sm[];
    const int which = blockIdx.x / NBN;
    const int bn = (blockIdx.x % NBN) * BN;
    const int bm = blockIdx.y * BM;

    const __half* W = Wall + (size_t)which * D_ * D_;
    EpiQKV epi;
    epi.bias  = (which == 0) ? bq : (which == 1) ? bk : bv;
    epi.C     = (which == 0) ? Qh : (which == 1) ? Kh : Vh;
    epi.which = which;
    epi.M     = M;

    gemm_body(A, W, sm, bm, bn, M, epi);
}

// ---------------------------------------------------------------------------
// Plain GEMM + bias, fp32 output (final projection)
// ---------------------------------------------------------------------------
__global__ __launch_bounds__(256, 2) void gemm_out_kernel(
    const __half* __restrict__ A, const __half* __restrict__ W,
    const float* __restrict__ bias, float* __restrict__ C, int M)
{
    extern __shared__ __align__(128) char sm[];
    const int bn = blockIdx.x * BN;
    const int bm = blockIdx.y * BM;

    EpiOut epi; epi.bias = bias; epi.C = C; epi.M = M;
    gemm_body(A, W, sm, bm, bn, M, epi);
}

// ---------------------------------------------------------------------------
// Fused flash attention on mma.f16 (unchanged, proven).
// ---------------------------------------------------------------------------
#define QT   128
#define KT   32
#define QSTR 100
#define VSTR 36

__global__ __launch_bounds__(256) void attn_mma_kernel(
    const __half* __restrict__ Q, const __half* __restrict__ K,
    const __half* __restrict__ V, __half* __restrict__ O)
{
    __shared__ __align__(16) __half Qs[QT * QSTR];
    __shared__ __align__(16) __half Ks[KT * QSTR];
    __shared__ __align__(16) __half Vs[HD_ * VSTR];

    const int qt = blockIdx.x, h = blockIdx.y, b = blockIdx.z;
    const int q0 = qt * QT;
    const int t = threadIdx.x, lane = t & 31, wid = t >> 5;
    const int g = lane >> 2, tc = lane & 3;

    for (int idx = t; idx < QT * 24; idx += 256) {
        int r = idx / 24, c = idx % 24;
        int s = q0 + r; if (s >= SEQ_) s = SEQ_ - 1;
        uint2 v = make_uint2(0u, 0u);
        if (c < 22)
            v = *(const uint2*)&Q[(((size_t)b * SEQ_ + s) * H_ + h) * HD_ + c * 4];
        *(uint2*)&Qs[r * QSTR + c * 4] = v;
    }
    __syncthreads();

    const int rw = wid * 16;
    uint32_t qf[6][4];
#pragma unroll
    for (int ks = 0; ks < 6; ks++) {
        const __half* p0 = &Qs[(rw + g) * QSTR + ks * 16 + 2 * tc];
        const __half* p1 = p0 + 8 * QSTR;
        qf[ks][0] = *(const uint32_t*)p0;
        qf[ks][1] = *(const uint32_t*)p1;
        qf[ks][2] = *(const uint32_t*)(p0 + 8);
        qf[ks][3] = *(const uint32_t*)(p1 + 8);
    }
    __syncthreads();

    float oacc[11][4];
#pragma unroll
    for (int nt = 0; nt < 11; nt++)
#pragma unroll
        for (int i = 0; i < 4; i++) oacc[nt][i] = 0.f;
    float m0 = -1e30f, m1 = -1e30f, l0 = 0.f, l1 = 0.f;

    for (int k0 = 0; k0 < SEQ_; k0 += KT) {
        for (int idx = t; idx < KT * 24; idx += 256) {
            int r = idx / 24, c = idx % 24;
            int s = k0 + r;
            uint2 v = make_uint2(0u, 0u);
            if (s < SEQ_ && c < 22)
                v = *(const uint2*)&K[(((size_t)b * SEQ_ + s) * H_ + h) * HD_ + c * 4];
            *(uint2*)&Ks[r * QSTR + c * 4] = v;
        }
        for (int idx = t; idx < KT * 22; idx += 256) {
            int r = idx / 22, c = idx % 22;
            int s = k0 + r;
            uint2 v = make_uint2(0u, 0u);
            if (s < SEQ_)
                v = *(const uint2*)&V[(((size_t)b * SEQ_ + s) * H_ + h) * HD_ + c * 4];
            __half h4[4];
            *(uint2*)h4 = v;
#pragma unroll
            for (int j = 0; j < 4; j++)
                Vs[(c * 4 + j) * VSTR + r] = h4[j];
        }
        __syncthreads();

        float sc[4][4];
#pragma unroll
        for (int nt = 0; nt < 4; nt++)
#pragma unroll
            for (int i = 0; i < 4; i++) sc[nt][i] = 0.f;

#pragma unroll
        for (int ks = 0; ks < 6; ks++) {
#pragma unroll
            for (int nt = 0; nt < 4; nt++) {
                const __half* p = &Ks[(nt * 8 + g) * QSTR + ks * 16 + 2 * tc];
                uint32_t bf[2];
                bf[0] = *(const uint32_t*)p;
                bf[1] = *(const uint32_t*)(p + 8);
                mma_f16(sc[nt], qf[ks], bf);
            }
        }

        if (k0 + KT > SEQ_) {
#pragma unroll
            for (int nt = 0; nt < 4; nt++) {
                int kidx = k0 + nt * 8 + 2 * tc;
                if (kidx >= SEQ_)     { sc[nt][0] = -1e30f; sc[nt][2] = -1e30f; }
                if (kidx + 1 >= SEQ_) { sc[nt][1] = -1e30f; sc[nt][3] = -1e30f; }
            }
        }

        float mx0 = sc[0][0], mx1 = sc[0][2];
#pragma unroll
        for (int nt = 0; nt < 4; nt++) {
            mx0 = fmaxf(mx0, fmaxf(sc[nt][0], sc[nt][1]));
            mx1 = fmaxf(mx1, fmaxf(sc[nt][2], sc[nt][3]));
        }
        mx0 = fmaxf(mx0, __shfl_xor_sync(0xffffffffu, mx0, 1));
        mx0 = fmaxf(mx0, __shfl_xor_sync(0xffffffffu, mx0, 2));
        mx1 = fmaxf(mx1, __shfl_xor_sync(0xffffffffu, mx1, 1));
        mx1 = fmaxf(mx1, __shfl_xor_sync(0xffffffffu, mx1, 2));
        mx0 = fmaxf(mx0, m0); mx1 = fmaxf(mx1, m1);
        float corr0 = __expf(m0 - mx0), corr1 = __expf(m1 - mx1);
        m0 = mx0; m1 = mx1;

        float s0 = 0.f, s1 = 0.f;
#pragma unroll
        for (int nt = 0; nt < 4; nt++) {
            sc[nt][0] = __expf(sc[nt][0] - m0);
            sc[nt][1] = __expf(sc[nt][1] - m0);
            sc[nt][2] = __expf(sc[nt][2] - m1);
            sc[nt][3] = __expf(sc[nt][3] - m1);
            s0 += sc[nt][0] + sc[nt][1];
            s1 += sc[nt][2] + sc[nt][3];
        }
        s0 += __shfl_xor_sync(0xffffffffu, s0, 1);
        s0 += __shfl_xor_sync(0xffffffffu, s0, 2);
        s1 += __shfl_xor_sync(0xffffffffu, s1, 1);
        s1 += __shfl_xor_sync(0xffffffffu, s1, 2);
        l0 = l0 * corr0 + s0;
        l1 = l1 * corr1 + s1;

#pragma unroll
        for (int nt = 0; nt < 11; nt++) {
            oacc[nt][0] *= corr0; oacc[nt][1] *= corr0;
            oacc[nt][2] *= corr1; oacc[nt][3] *= corr1;
        }

        uint32_t pf[2][4];
#pragma unroll
        for (int kv = 0; kv < 2; kv++) {
            pf[kv][0] = packh2(sc[2 * kv][0],     sc[2 * kv][1]);
            pf[kv][1] = packh2(sc[2 * kv][2],     sc[2 * kv][3]);
            pf[kv][2] = packh2(sc[2 * kv + 1][0], sc[2 * kv + 1][1]);
            pf[kv][3] = packh2(sc[2 * kv + 1][2], sc[2 * kv + 1][3]);
        }

#pragma unroll
        for (int kv = 0; kv < 2; kv++) {
#pragma unroll
            for (int nt = 0; nt < 11; nt++) {
                const __half* p = &Vs[(nt * 8 + g) * VSTR + kv * 16 + 2 * tc];
                uint32_t bf[2];
                bf[0] = *(const uint32_t*)p;
                bf[1] = *(const uint32_t*)(p + 8);
                mma_f16(oacc[nt], pf[kv], bf);
            }
        }
        __syncthreads();
    }

    float inv0 = 1.f / l0, inv1 = 1.f / l1;
    int s0 = q0 + rw + g, s1 = s0 + 8;
#pragma unroll
    for (int nt = 0; nt < 11; nt++) {
        int d = nt * 8 + 2 * tc;
        if (s0 < SEQ_)
            *(__half2*)&O[(((size_t)b * SEQ_ + s0) * H_ + h) * HD_ + d] =
                __floats2half2_rn(oacc[nt][0] * inv0, oacc[nt][1] * inv0);
        if (s1 < SEQ_)
            *(__half2*)&O[(((size_t)b * SEQ_ + s1) * H_ + h) * HD_ + d] =
                __floats2half2_rn(oacc[nt][2] * inv1, oacc[nt][3] * inv1);
    }
}

// ---------------------------------------------------------------------------
extern "C" void kernel_launch(void* const* d_in, const int* in_sizes, int n_in,
                              void* d_out, int out_size)
{
    const float* X  = (const float*)d_in[0];
    const float* wq = (const float*)d_in[1];
    const float* bq = (const float*)d_in[2];
    const float* wk = (const float*)d_in[3];
    const float* bk = (const float*)d_in[4];
    const float* wv = (const float*)d_in[5];
    const float* bv = (const float*)d_in[6];
    const float* wo = (const float*)d_in[7];
    const float* bo = (const float*)d_in[8];
    float* out = (float*)d_out;

    __half *Qh, *Kh, *Vh, *Xh, *Wh;
    cudaGetSymbolAddress((void**)&Qh, g_Qh);
    cudaGetSymbolAddress((void**)&Kh, g_Kh);
    cudaGetSymbolAddress((void**)&Vh, g_Vh);
    cudaGetSymbolAddress((void**)&Xh, g_Xh);
    cudaGetSymbolAddress((void**)&Wh, g_Wh);

    cudaFuncSetAttribute(gemm_qkv_kernel,
                         cudaFuncAttributeMaxDynamicSharedMemorySize, GSMEM);
    cudaFuncSetAttribute(gemm_out_kernel,
                         cudaFuncAttributeMaxDynamicSharedMemorySize, GSMEM);

    const int WN4 = D_ * D_ / 4;
    const int XN4 = M_ * D_ / 4;
    f2h_kernel<<<(XN4 + 255) / 256, 256>>>(X, Xh, XN4);
    dim3 wgrid((WN4 + 255) / 256, 4);
    f2h4_kernel<<<wgrid, 256>>>(wq, wk, wv, wo, Wh, WN4);
    rope_init_kernel<<<(SEQ_ * 44 + 255) / 256, 256>>>();

    dim3 qgrid(3 * NBN, (M_ + BM - 1) / BM);   // (33, 145)
    gemm_qkv_kernel<<<qgrid, 256, GSMEM>>>(Xh, Wh, bq, bk, bv, Qh, Kh, Vh, M_);

    dim3 agrid((SEQ_ + QT - 1) / QT, H_, B_);  // (5, 16, 32)
    attn_mma_kernel<<<agrid, 256>>>(Qh, Kh, Vh, Xh);

    dim3 ogrid(NBN, (M_ + BM - 1) / BM);       // (11, 145)
    gemm_out_kernel<<<ogrid, 256, GSMEM>>>(Xh, Wh + 3 * (size_t)D_ * D_, bo, out, M_);
}